// round 7
// baseline (speedup 1.0000x reference)
#include <cuda_runtime.h>
#include <cuda_fp16.h>
#include <cstdint>

#define B_ 64
#define T_ 256
#define D_ 768
#define NH_ 12
#define C_ 7
#define DH_ 64

// Scratch (device globals — no allocation allowed)
__device__ float  g_q[B_ * T_ * D_];
__device__ float  g_k[B_ * T_ * D_];
__device__ float  g_v[B_ * T_ * D_];
__device__ float  g_c[B_ * T_ * D_];
__device__ float  g_all[B_ * T_ * C_];
__device__ __half g_h16[B_ * T_ * D_];     // H in half
__device__ __half g_ctx16[B_ * T_ * D_];   // attention output in half
__device__ __half g_wt16[4 * D_ * D_];     // Wq^T,Wk^T,Wv^T,Wo^T (K-major, half)

// ---------------------------------------------------------------------------
__device__ __forceinline__ uint32_t smem_u32(const void* p) {
    uint32_t a;
    asm("{ .reg .u64 t; cvta.to.shared.u64 t, %1; cvt.u32.u64 %0, t; }" : "=r"(a) : "l"(p));
    return a;
}
__device__ __forceinline__ void cp_async16(uint32_t saddr, const void* src) {
    asm volatile("cp.async.cg.shared.global [%0], [%1], 16;" :: "r"(saddr), "l"(src) : "memory");
}
__device__ __forceinline__ void cp_commit() { asm volatile("cp.async.commit_group;" ::: "memory"); }
__device__ __forceinline__ void cp_wait0()  { asm volatile("cp.async.wait_group 0;" ::: "memory"); }
__device__ __forceinline__ void cp_wait1()  { asm volatile("cp.async.wait_group 1;" ::: "memory"); }

__device__ __forceinline__ void mma_f16(float c[4], const uint32_t a[4], const uint32_t b[2]) {
    asm volatile(
        "mma.sync.aligned.m16n8k16.row.col.f32.f16.f16.f32 "
        "{%0,%1,%2,%3},{%4,%5,%6,%7},{%8,%9},{%0,%1,%2,%3};"
        : "+f"(c[0]), "+f"(c[1]), "+f"(c[2]), "+f"(c[3])
        : "r"(a[0]), "r"(a[1]), "r"(a[2]), "r"(a[3]), "r"(b[0]), "r"(b[1]));
}

// ---------------------------------------------------------------------------
// Conversions
// ---------------------------------------------------------------------------
__global__ void conv_f2h(const float4* __restrict__ src, __half2* __restrict__ dst, int n4)
{
    int i = blockIdx.x * blockDim.x + threadIdx.x;
    if (i < n4) {
        float4 v = src[i];
        dst[2 * i]     = __floats2half2_rn(v.x, v.y);
        dst[2 * i + 1] = __floats2half2_rn(v.z, v.w);
    }
}

// g_wt16[z][n][k] = (half) W_z[k][n]
__global__ void transpose4(const float* __restrict__ Wq, const float* __restrict__ Wk,
                           const float* __restrict__ Wv, const float* __restrict__ Wo)
{
    __shared__ float t[32][33];
    const float* src = (blockIdx.z == 0) ? Wq : (blockIdx.z == 1) ? Wk :
                       (blockIdx.z == 2) ? Wv : Wo;
    __half* dst = g_wt16 + (size_t)blockIdx.z * D_ * D_;
    int x = blockIdx.x * 32 + threadIdx.x;
    int y = blockIdx.y * 32 + threadIdx.y;
    #pragma unroll
    for (int i = 0; i < 32; i += 8)
        t[threadIdx.y + i][threadIdx.x] = src[(size_t)(y + i) * D_ + x];
    __syncthreads();
    x = blockIdx.y * 32 + threadIdx.x;
    y = blockIdx.x * 32 + threadIdx.y;
    #pragma unroll
    for (int i = 0; i < 32; i += 8)
        dst[(size_t)(y + i) * D_ + x] = __float2half(t[threadIdx.x][threadIdx.y + i]);
}

// ---------------------------------------------------------------------------
// FP16 tensor-core GEMM: Out[M,N] = A[M,K] @ WT[N,K]^T + bias[N]   (fp32 accum)
// ---------------------------------------------------------------------------
#define HST 40                          // smem row stride in halves (80 B)
#define HSTAGE (128 * HST * 2 * 2)      // bytes = 20480
#define HBK 32
#define HKT (D_ / HBK)                  // 24

__global__ __launch_bounds__(256, 2) void f16_gemm_bias(
    const __half* __restrict__ A, const __half* __restrict__ WTbase,
    const float* __restrict__ b0, float* __restrict__ O0,
    const float* __restrict__ b1, float* __restrict__ O1,
    const float* __restrict__ b2, float* __restrict__ O2)
{
    __shared__ __align__(16) char gsm[2 * HSTAGE];
    const uint32_t sbase = smem_u32(gsm);

    const int tid = threadIdx.x;
    const int bx = blockIdx.x, by = blockIdx.y, bz = blockIdx.z;

    const __half* W    = WTbase + (size_t)bz * D_ * D_;
    const float*  bias = (bz == 0) ? b0 : (bz == 1) ? b1 : b2;
    float*        Cout = (bz == 0) ? O0 : (bz == 1) ? O1 : O2;

    const int warp = tid >> 5;
    const int lane = tid & 31;
    const int gid = lane >> 2;
    const int tig = lane & 3;
    const int m0 = (warp & 3) * 32;
    const int n0 = (warp >> 2) * 64;

    const __half* Ag = A + (size_t)(by * 128) * D_;
    const __half* Wg = W + (size_t)(bx * 128) * D_;

    const int frow = tid >> 1;
    const int g0   = (tid & 1) * 2;

    float acc[2][8][4] = {};

    #define HFILL(buf, kt) do {                                                   \
        const uint32_t sa = sbase + (buf) * HSTAGE;                               \
        const uint32_t sb = sa + 128 * HST * 2;                                   \
        const int kb = (kt) * HBK;                                                \
        _Pragma("unroll")                                                         \
        for (int g = g0; g < g0 + 2; g++) {                                       \
            cp_async16(sa + frow * (HST * 2) + g * 16,                            \
                       Ag + (size_t)frow * D_ + kb + g * 8);                      \
            cp_async16(sb + frow * (HST * 2) + g * 16,                            \
                       Wg + (size_t)frow * D_ + kb + g * 8);                      \
        }                                                                         \
    } while (0)

    HFILL(0, 0);
    cp_commit();

    for (int kt = 0; kt < HKT; kt++) {
        const int buf = kt & 1;
        if (kt + 1 < HKT) HFILL(buf ^ 1, kt + 1);
        cp_commit();
        cp_wait1();
        __syncthreads();

        const __half* sA = (const __half*)(gsm + buf * HSTAGE);
        const __half* sB = sA + 128 * HST;

        #pragma unroll
        for (int kk = 0; kk < HBK; kk += 16) {
            uint32_t a[2][4], b[8][2];
            #pragma unroll
            for (int mt = 0; mt < 2; mt++) {
                int mr = m0 + mt * 16 + gid;
                a[mt][0] = *(const uint32_t*)&sA[mr * HST + kk + 2 * tig];
                a[mt][1] = *(const uint32_t*)&sA[(mr + 8) * HST + kk + 2 * tig];
                a[mt][2] = *(const uint32_t*)&sA[mr * HST + kk + 2 * tig + 8];
                a[mt][3] = *(const uint32_t*)&sA[(mr + 8) * HST + kk + 2 * tig + 8];
            }
            #pragma unroll
            for (int nt = 0; nt < 8; nt++) {
                int nc = n0 + nt * 8 + gid;
                b[nt][0] = *(const uint32_t*)&sB[nc * HST + kk + 2 * tig];
                b[nt][1] = *(const uint32_t*)&sB[nc * HST + kk + 2 * tig + 8];
            }
            #pragma unroll
            for (int mt = 0; mt < 2; mt++)
                #pragma unroll
                for (int nt = 0; nt < 8; nt++)
                    mma_f16(acc[mt][nt], a[mt], b[nt]);
        }
        __syncthreads();
    }
    cp_wait0();

    #pragma unroll
    for (int mt = 0; mt < 2; mt++) {
        #pragma unroll
        for (int nt = 0; nt < 8; nt++) {
            int row = by * 128 + m0 + mt * 16 + gid;
            int col = bx * 128 + n0 + nt * 8 + tig * 2;
            float bx0 = bias[col], bx1 = bias[col + 1];
            float2 o0 = {acc[mt][nt][0] + bx0, acc[mt][nt][1] + bx1};
            float2 o1 = {acc[mt][nt][2] + bx0, acc[mt][nt][3] + bx1};
            *(float2*)(Cout + (size_t)row * D_ + col) = o0;
            *(float2*)(Cout + (size_t)(row + 8) * D_ + col) = o1;
        }
    }
}

// ---------------------------------------------------------------------------
// Attention v3: 2 threads per query (each owns 32 dims), 4-key batching.
// Warp-uniform key-loop bound (shfl-safe); per-thread masking for validity.
// Block = 256 threads = 128 queries; grid (NH, B, 2).
// ---------------------------------------------------------------------------
__global__ __launch_bounds__(256) void attn_kernel(const int* __restrict__ num_turns)
{
    const int h = blockIdx.x;
    const int b = blockIdx.y;
    const int qbase = blockIdx.z * 128;
    const int tid = threadIdx.x;
    const int warp = tid >> 5;
    const int q = qbase + (tid >> 1);
    const int part = tid & 1;

    __shared__ float Ks[64][64];
    __shared__ float Vs[64][64];

    const int nt = num_turns[b];
    const int limit = (q < nt) ? q : nt;                 // per-thread valid keys
    // warp-uniform max key count: highest query in this warp
    const int qwmax = qbase + warp * 16 + 15;
    const int wlimit = (qwmax < nt) ? qwmax : nt;
    // block-wide chunk count
    int blkmax = qbase + 127; if (nt < blkmax) blkmax = nt;
    if (T_ - 1 < blkmax) blkmax = T_ - 1;
    const int nchunks = (blkmax + 63) >> 6;

    const float* qptr = g_q + ((size_t)(b * T_ + q)) * D_ + h * DH_ + part * 32;
    float qr[32];
    #pragma unroll
    for (int d = 0; d < 32; d += 4) {
        float4 v = *(const float4*)(qptr + d);
        qr[d] = v.x; qr[d + 1] = v.y; qr[d + 2] = v.z; qr[d + 3] = v.w;
    }

    float m = -1e30f, l = 0.f;
    float acc[32] = {};
    const float scale = 0.125f;

    for (int ch = 0; ch < nchunks; ch++) {
        const int kbase = ch * 64;
        {
            int r  = tid >> 2;
            int c0 = (tid & 3) * 16;
            const float* kp = g_k + ((size_t)(b * T_ + kbase + r)) * D_ + h * DH_ + c0;
            const float* vp = g_v + ((size_t)(b * T_ + kbase + r)) * D_ + h * DH_ + c0;
            #pragma unroll
            for (int j = 0; j < 16; j += 4) {
                *(float4*)(&Ks[r][c0 + j]) = *(const float4*)(kp + j);
                *(float4*)(&Vs[r][c0 + j]) = *(const float4*)(vp + j);
            }
        }
        __syncthreads();

        // warp-uniform loop bound; per-thread valid-key bound
        int kend_w = wlimit - kbase; if (kend_w > 64) kend_w = 64;
        int kend_t = limit  - kbase; if (kend_t > 64) kend_t = 64;

        for (int kk = 0; kk < kend_w; kk += 4) {
            // 4 independent partial dots over this thread's 32 dims
            float sp[4];
            #pragma unroll
            for (int j = 0; j < 4; j++) {
                const float4* kr = (const float4*)(&Ks[(kk + j) & 63][part * 32]);
                float a0 = 0.f, a1 = 0.f, a2 = 0.f, a3 = 0.f;
                #pragma unroll
                for (int i = 0; i < 8; i++) {
                    float4 kv = kr[i];
                    a0 = fmaf(qr[4 * i    ], kv.x, a0);
                    a1 = fmaf(qr[4 * i + 1], kv.y, a1);
                    a2 = fmaf(qr[4 * i + 2], kv.z, a2);
                    a3 = fmaf(qr[4 * i + 3], kv.w, a3);
                }
                sp[j] = (a0 + a1) + (a2 + a3);
            }
            // combine halves (all 32 lanes execute: bound is warp-uniform)
            float s[4];
            bool valid[4];
            #pragma unroll
            for (int j = 0; j < 4; j++) {
                float o = __shfl_xor_sync(0xffffffff, sp[j], 1);
                valid[j] = (kk + j) < kend_t;
                s[j] = valid[j] ? (sp[j] + o) * scale : -1e30f;
            }
            // one rescale per 4 keys (masked keys can't raise the max)
            float mx = fmaxf(fmaxf(s[0], s[1]), fmaxf(s[2], s[3]));
            if (mx > m) {
                float corr = __expf(m - mx);
                m = mx;
                l *= corr;
                #pragma unroll
                for (int d = 0; d < 32; d++) acc[d] *= corr;
            }
            float p0 = valid[0] ? __expf(s[0] - m) : 0.f;
            float p1 = valid[1] ? __expf(s[1] - m) : 0.f;
            float p2 = valid[2] ? __expf(s[2] - m) : 0.f;
            float p3 = valid[3] ? __expf(s[3] - m) : 0.f;
            l += (p0 + p1) + (p2 + p3);

            const float4* v0 = (const float4*)(&Vs[(kk    ) & 63][part * 32]);
            const float4* v1 = (const float4*)(&Vs[(kk + 1) & 63][part * 32]);
            const float4* v2 = (const float4*)(&Vs[(kk + 2) & 63][part * 32]);
            const float4* v3 = (const float4*)(&Vs[(kk + 3) & 63][part * 32]);
            #pragma unroll
            for (int i = 0; i < 8; i++) {
                float4 a = v0[i], bb = v1[i], c = v2[i], dd = v3[i];
                acc[4 * i    ] = fmaf(p0, a.x, fmaf(p1, bb.x, fmaf(p2, c.x, fmaf(p3, dd.x, acc[4 * i    ]))));
                acc[4 * i + 1] = fmaf(p0, a.y, fmaf(p1, bb.y, fmaf(p2, c.y, fmaf(p3, dd.y, acc[4 * i + 1]))));
                acc[4 * i + 2] = fmaf(p0, a.z, fmaf(p1, bb.z, fmaf(p2, c.z, fmaf(p3, dd.z, acc[4 * i + 2]))));
                acc[4 * i + 3] = fmaf(p0, a.w, fmaf(p1, bb.w, fmaf(p2, c.w, fmaf(p3, dd.w, acc[4 * i + 3]))));
            }
        }
        __syncthreads();
    }

    __half2* op = (__half2*)(g_ctx16 + ((size_t)(b * T_ + q)) * D_ + h * DH_ + part * 32);
    if (limit > 0) {
        float invl = 1.f / l;
        #pragma unroll
        for (int d = 0; d < 32; d += 2)
            op[d >> 1] = __floats2half2_rn(acc[d] * invl, acc[d + 1] * invl);
    } else {
        __half2 z = __floats2half2_rn(0.f, 0.f);
        #pragma unroll
        for (int d = 0; d < 32; d += 2) op[d >> 1] = z;
    }
}

// ---------------------------------------------------------------------------
// Classifier
// ---------------------------------------------------------------------------
#define CL_ROWS 16
#define CL_THREADS 192

__global__ __launch_bounds__(CL_THREADS) void classifier_kernel(
    const float* __restrict__ H, const float* __restrict__ Wc,
    const float* __restrict__ bc)
{
    __shared__ float sWc[2 * D_ * C_];
    __shared__ float sred[6 * C_];

    const int tid = threadIdx.x;
    for (int i = tid; i < 2 * D_ * C_; i += CL_THREADS) sWc[i] = Wc[i];
    __syncthreads();

    const int d0 = tid * 4;
    const int row0 = blockIdx.x * CL_ROWS;

    for (int r = 0; r < CL_ROWS; r++) {
        const int row = row0 + r;
        const int t = row & (T_ - 1);
        float facc[C_] = {};
        {
            float4 hv = *(const float4*)(H + (size_t)row * D_ + d0);
            #pragma unroll
            for (int c = 0; c < C_; c++) {
                facc[c] = fmaf(hv.x, sWc[(d0    ) * C_ + c], facc[c]);
                facc[c] = fmaf(hv.y, sWc[(d0 + 1) * C_ + c], facc[c]);
                facc[c] = fmaf(hv.z, sWc[(d0 + 2) * C_ + c], facc[c]);
                facc[c] = fmaf(hv.w, sWc[(d0 + 3) * C_ + c], facc[c]);
            }
            if (t > 0) {
                float4 cv = *(const float4*)(g_c + (size_t)row * D_ + d0);
                #pragma unroll
                for (int c = 0; c < C_; c++) {
                    facc[c] = fmaf(cv.x, sWc[(D_ + d0    ) * C_ + c], facc[c]);
                    facc[c] = fmaf(cv.y, sWc[(D_ + d0 + 1) * C_ + c], facc[c]);
                    facc[c] = fmaf(cv.z, sWc[(D_ + d0 + 2) * C_ + c], facc[c]);
                    facc[c] = fmaf(cv.w, sWc[(D_ + d0 + 3) * C_ + c], facc[c]);
                }
            }
        }
        #pragma unroll
        for (int c = 0; c < C_; c++)
            #pragma unroll
            for (int off = 16; off; off >>= 1)
                facc[c] += __shfl_down_sync(0xffffffff, facc[c], off);
        if ((tid & 31) == 0) {
            int w = tid >> 5;
            #pragma unroll
            for (int c = 0; c < C_; c++) sred[w * C_ + c] = facc[c];
        }
        __syncthreads();
        if (tid < C_) {
            float s = bc[tid];
            #pragma unroll
            for (int w = 0; w < 6; w++) s += sred[w * C_ + tid];
            g_all[(size_t)row * C_ + tid] = s;
        }
        __syncthreads();
    }
}

// ---------------------------------------------------------------------------
__global__ void finalize_kernel(const int* __restrict__ nt, float* __restrict__ out,
                                int out_size)
{
    const int ALL = B_ * T_ * C_;
    const int FIN = B_ * C_;
    int i = blockIdx.x * blockDim.x + threadIdx.x;
    if (out_size >= ALL + FIN) {
        if (i < ALL) out[i] = g_all[i];
        if (i < FIN) {
            int b = i / C_, c = i - b * C_;
            int t = nt[b] - 1;
            out[ALL + i] = g_all[((size_t)(b * T_ + t)) * C_ + c];
        }
    } else if (out_size >= ALL) {
        if (i < ALL) out[i] = g_all[i];
    } else {
        if (i < FIN) {
            int b = i / C_, c = i - b * C_;
            int t = nt[b] - 1;
            out[i] = g_all[((size_t)(b * T_ + t)) * C_ + c];
        }
    }
}

// ---------------------------------------------------------------------------
extern "C" void kernel_launch(void* const* d_in, const int* in_sizes, int n_in,
                              void* d_out, int out_size)
{
    const float* H  = (const float*)d_in[0];
    const float* Wq = (const float*)d_in[1];
    const float* bq = (const float*)d_in[2];
    const float* Wk = (const float*)d_in[3];
    const float* bk = (const float*)d_in[4];
    const float* Wv = (const float*)d_in[5];
    const float* bv = (const float*)d_in[6];
    const float* Wo = (const float*)d_in[7];
    const float* bo = (const float*)d_in[8];
    const float* Wc = (const float*)d_in[9];
    const float* bc = (const float*)d_in[10];
    const int*   nt = (const int*)d_in[11];
    float* out = (float*)d_out;

    float *pq, *pk, *pv, *pc;
    __half *ph16, *pctx16, *pwt16;
    cudaGetSymbolAddress((void**)&pq,     g_q);
    cudaGetSymbolAddress((void**)&pk,     g_k);
    cudaGetSymbolAddress((void**)&pv,     g_v);
    cudaGetSymbolAddress((void**)&pc,     g_c);
    cudaGetSymbolAddress((void**)&ph16,   g_h16);
    cudaGetSymbolAddress((void**)&pctx16, g_ctx16);
    cudaGetSymbolAddress((void**)&pwt16,  g_wt16);

    const int M = B_ * T_;

    // 0) conversions
    const int n4 = M * D_ / 4;
    conv_f2h<<<(n4 + 255) / 256, 256>>>((const float4*)H, (__half2*)ph16, n4);
    transpose4<<<dim3(D_ / 32, D_ / 32, 4), dim3(32, 8)>>>(Wq, Wk, Wv, Wo);

    // 1) fused QKV
    dim3 qkv_grid(D_ / 128, M / 128, 3);
    f16_gemm_bias<<<qkv_grid, 256>>>(ph16, pwt16, bq, pq, bk, pk, bv, pv);

    // 2) attention (2 q-tiles per (h,b))
    attn_kernel<<<dim3(NH_, B_, 2), 256>>>(nt);

    // 3) out-proj
    dim3 o_grid(D_ / 128, M / 128, 1);
    f16_gemm_bias<<<o_grid, 256>>>(pctx16, pwt16 + (size_t)3 * D_ * D_, bo, pc, bo, pc, bo, pc);

    // 4) classifier + 5) finalize
    classifier_kernel<<<M / CL_ROWS, CL_THREADS>>>(H, Wc, bc);

    const int ALL = B_ * T_ * C_;
    finalize_kernel<<<(ALL + 255) / 256, 256>>>(nt, out, out_size);
}

// round 8
// speedup vs baseline: 1.7917x; 1.7917x over previous
#include <cuda_runtime.h>
#include <cuda_fp16.h>
#include <cstdint>

#define B_ 64
#define T_ 256
#define D_ 768
#define NH_ 12
#define C_ 7
#define DH_ 64

// Scratch (device globals — no allocation allowed)
__device__ float  g_q[B_ * T_ * D_];
__device__ float  g_k[B_ * T_ * D_];
__device__ float  g_v[B_ * T_ * D_];
__device__ float  g_c[B_ * T_ * D_];
__device__ float  g_all[B_ * T_ * C_];
__device__ __half g_h16[B_ * T_ * D_];     // H in half
__device__ __half g_ctx16[B_ * T_ * D_];   // attention output in half
__device__ __half g_wt16[4 * D_ * D_];     // Wq^T,Wk^T,Wv^T,Wo^T (K-major, half)

// ---------------------------------------------------------------------------
__device__ __forceinline__ uint32_t smem_u32(const void* p) {
    uint32_t a;
    asm("{ .reg .u64 t; cvta.to.shared.u64 t, %1; cvt.u32.u64 %0, t; }" : "=r"(a) : "l"(p));
    return a;
}
__device__ __forceinline__ void cp_async16(uint32_t saddr, const void* src) {
    asm volatile("cp.async.cg.shared.global [%0], [%1], 16;" :: "r"(saddr), "l"(src) : "memory");
}
__device__ __forceinline__ void cp_commit() { asm volatile("cp.async.commit_group;" ::: "memory"); }
__device__ __forceinline__ void cp_wait0()  { asm volatile("cp.async.wait_group 0;" ::: "memory"); }
__device__ __forceinline__ void cp_wait1()  { asm volatile("cp.async.wait_group 1;" ::: "memory"); }

__device__ __forceinline__ void mma_f16(float c[4], const uint32_t a[4], const uint32_t b[2]) {
    asm volatile(
        "mma.sync.aligned.m16n8k16.row.col.f32.f16.f16.f32 "
        "{%0,%1,%2,%3},{%4,%5,%6,%7},{%8,%9},{%0,%1,%2,%3};"
        : "+f"(c[0]), "+f"(c[1]), "+f"(c[2]), "+f"(c[3])
        : "r"(a[0]), "r"(a[1]), "r"(a[2]), "r"(a[3]), "r"(b[0]), "r"(b[1]));
}
__device__ __forceinline__ void ldsm_x4(uint32_t& r0, uint32_t& r1, uint32_t& r2, uint32_t& r3,
                                        uint32_t addr) {
    asm volatile("ldmatrix.sync.aligned.m8n8.x4.shared.b16 {%0,%1,%2,%3}, [%4];"
                 : "=r"(r0), "=r"(r1), "=r"(r2), "=r"(r3) : "r"(addr));
}

// ---------------------------------------------------------------------------
// Conversions
// ---------------------------------------------------------------------------
__global__ void conv_f2h(const float4* __restrict__ src, __half2* __restrict__ dst, int n4)
{
    int i = blockIdx.x * blockDim.x + threadIdx.x;
    if (i < n4) {
        float4 v = src[i];
        dst[2 * i]     = __floats2half2_rn(v.x, v.y);
        dst[2 * i + 1] = __floats2half2_rn(v.z, v.w);
    }
}

// g_wt16[z][n][k] = (half) W_z[k][n]
__global__ void transpose4(const float* __restrict__ Wq, const float* __restrict__ Wk,
                           const float* __restrict__ Wv, const float* __restrict__ Wo)
{
    __shared__ float t[32][33];
    const float* src = (blockIdx.z == 0) ? Wq : (blockIdx.z == 1) ? Wk :
                       (blockIdx.z == 2) ? Wv : Wo;
    __half* dst = g_wt16 + (size_t)blockIdx.z * D_ * D_;
    int x = blockIdx.x * 32 + threadIdx.x;
    int y = blockIdx.y * 32 + threadIdx.y;
    #pragma unroll
    for (int i = 0; i < 32; i += 8)
        t[threadIdx.y + i][threadIdx.x] = src[(size_t)(y + i) * D_ + x];
    __syncthreads();
    x = blockIdx.y * 32 + threadIdx.x;
    y = blockIdx.x * 32 + threadIdx.y;
    #pragma unroll
    for (int i = 0; i < 32; i += 8)
        dst[(size_t)(y + i) * D_ + x] = __float2half(t[threadIdx.x][threadIdx.y + i]);
}

// ---------------------------------------------------------------------------
// FP16 tensor-core GEMM: Out[M,N] = A[M,K] @ WT[N,K]^T + bias[N]   (fp32 accum)
// 128x128 tile, BK=32 halves, 256 threads (8 warps 4x2), warp tile 32x64.
// m16n8k16; 2-stage cp.async; ldmatrix.x4 fragment loads.
// ---------------------------------------------------------------------------
#define HST 40                          // smem row stride in halves (80 B)
#define HSTAGE (128 * HST * 2 * 2)      // bytes = 20480
#define HBK 32
#define HKT (D_ / HBK)                  // 24

__global__ __launch_bounds__(256, 2) void f16_gemm_bias(
    const __half* __restrict__ A, const __half* __restrict__ WTbase,
    const float* __restrict__ b0, float* __restrict__ O0,
    const float* __restrict__ b1, float* __restrict__ O1,
    const float* __restrict__ b2, float* __restrict__ O2)
{
    __shared__ __align__(16) char gsm[2 * HSTAGE];
    const uint32_t sbase = smem_u32(gsm);

    const int tid = threadIdx.x;
    const int bx = blockIdx.x, by = blockIdx.y, bz = blockIdx.z;

    const __half* W    = WTbase + (size_t)bz * D_ * D_;
    const float*  bias = (bz == 0) ? b0 : (bz == 1) ? b1 : b2;
    float*        Cout = (bz == 0) ? O0 : (bz == 1) ? O1 : O2;

    const int warp = tid >> 5;
    const int lane = tid & 31;
    const int gid = lane >> 2;
    const int tig = lane & 3;
    const int m0 = (warp & 3) * 32;
    const int n0 = (warp >> 2) * 64;

    const __half* Ag = A + (size_t)(by * 128) * D_;
    const __half* Wg = W + (size_t)(bx * 128) * D_;

    const int frow = tid >> 1;
    const int g0   = (tid & 1) * 2;

    // ldmatrix lane maps (byte offsets within a stage)
    const int a_r = ((lane >> 3) & 1) * 8 + (lane & 7);  // row within 16-row tile
    const int a_c = (lane >> 4) * 8;                     // col offset (halves)
    const int b_r = (lane >> 4) * 8 + (lane & 7);        // row within 16-n group
    const int b_c = ((lane >> 3) & 1) * 8;
    const uint32_t aoff0 = ((m0 + a_r) * HST + a_c) * 2;              // mt=0, kk=0
    const uint32_t boff0 = 128 * HST * 2 + ((n0 + b_r) * HST + b_c) * 2;  // jp=0, kk=0

    float acc[2][8][4] = {};

    #define HFILL(buf, kt) do {                                                   \
        const uint32_t sa = sbase + (buf) * HSTAGE;                               \
        const uint32_t sb = sa + 128 * HST * 2;                                   \
        const int kb = (kt) * HBK;                                                \
        _Pragma("unroll")                                                         \
        for (int g = g0; g < g0 + 2; g++) {                                       \
            cp_async16(sa + frow * (HST * 2) + g * 16,                            \
                       Ag + (size_t)frow * D_ + kb + g * 8);                      \
            cp_async16(sb + frow * (HST * 2) + g * 16,                            \
                       Wg + (size_t)frow * D_ + kb + g * 8);                      \
        }                                                                         \
    } while (0)

    HFILL(0, 0);
    cp_commit();

    for (int kt = 0; kt < HKT; kt++) {
        const int buf = kt & 1;
        if (kt + 1 < HKT) HFILL(buf ^ 1, kt + 1);
        cp_commit();
        cp_wait1();
        __syncthreads();

        const uint32_t stage = sbase + buf * HSTAGE;

        #pragma unroll
        for (int kk = 0; kk < HBK; kk += 16) {
            uint32_t a[2][4], b[8][2];
            // A fragments: 2 tiles of 16 rows
            ldsm_x4(a[0][0], a[0][1], a[0][2], a[0][3], stage + aoff0 + kk * 2);
            ldsm_x4(a[1][0], a[1][1], a[1][2], a[1][3], stage + aoff0 + 16 * HST * 2 + kk * 2);
            // B fragments: 4 groups of 16 n-rows (2 n-tiles each)
            #pragma unroll
            for (int jp = 0; jp < 4; jp++)
                ldsm_x4(b[2 * jp][0], b[2 * jp][1], b[2 * jp + 1][0], b[2 * jp + 1][1],
                        stage + boff0 + jp * 16 * HST * 2 + kk * 2);
            #pragma unroll
            for (int mt = 0; mt < 2; mt++)
                #pragma unroll
                for (int nt = 0; nt < 8; nt++)
                    mma_f16(acc[mt][nt], a[mt], b[nt]);
        }
        __syncthreads();
    }
    cp_wait0();

    #pragma unroll
    for (int mt = 0; mt < 2; mt++) {
        #pragma unroll
        for (int nt = 0; nt < 8; nt++) {
            int row = by * 128 + m0 + mt * 16 + gid;
            int col = bx * 128 + n0 + nt * 8 + tig * 2;
            float bx0 = bias[col], bx1 = bias[col + 1];
            float2 o0 = {acc[mt][nt][0] + bx0, acc[mt][nt][1] + bx1};
            float2 o1 = {acc[mt][nt][2] + bx0, acc[mt][nt][3] + bx1};
            *(float2*)(Cout + (size_t)row * D_ + col) = o0;
            *(float2*)(Cout + (size_t)(row + 8) * D_ + col) = o1;
        }
    }
}

// ---------------------------------------------------------------------------
// Attention (R5 structure + 2-key batching, no warp collectives):
// one block per (head, batch); one thread per query; online softmax.
// ---------------------------------------------------------------------------
__global__ __launch_bounds__(256) void attn_kernel(const int* __restrict__ num_turns)
{
    const int h = blockIdx.x;
    const int b = blockIdx.y;
    const int q = threadIdx.x;

    __shared__ float Ks[64][64];
    __shared__ float Vs[64][64];

    const int nt = num_turns[b];
    const int limit = (q < nt) ? q : nt;
    const int maxkeys = (T_ - 1 < nt) ? (T_ - 1) : nt;
    const int nchunks = (maxkeys + 63) >> 6;

    const float* qptr = g_q + ((size_t)(b * T_ + q)) * D_ + h * DH_;
    const float scale = 0.125f;  // 1/sqrt(64), folded into q
    float qr[64];
    #pragma unroll
    for (int d = 0; d < 64; d += 4) {
        float4 v = *(const float4*)(qptr + d);
        qr[d] = v.x * scale; qr[d + 1] = v.y * scale;
        qr[d + 2] = v.z * scale; qr[d + 3] = v.w * scale;
    }

    float m = -1e30f, l = 0.f;
    float acc[64] = {};

    for (int ch = 0; ch < nchunks; ch++) {
        const int kbase = ch * 64;
        {
            int r  = threadIdx.x >> 2;
            int c0 = (threadIdx.x & 3) * 16;
            const float* kp = g_k + ((size_t)(b * T_ + kbase + r)) * D_ + h * DH_ + c0;
            const float* vp = g_v + ((size_t)(b * T_ + kbase + r)) * D_ + h * DH_ + c0;
            #pragma unroll
            for (int j = 0; j < 16; j += 4) {
                *(float4*)(&Ks[r][c0 + j]) = *(const float4*)(kp + j);
                *(float4*)(&Vs[r][c0 + j]) = *(const float4*)(vp + j);
            }
        }
        __syncthreads();

        int kend = limit - kbase;
        if (kend > 64) kend = 64;

        for (int kk = 0; kk < kend; kk += 2) {
            const bool two = (kk + 1) < kend;
            const int k1 = (kk + 1) & 63;   // safe index for masked tail
            const float4* kr0 = (const float4*)(&Ks[kk][0]);
            const float4* kr1 = (const float4*)(&Ks[k1][0]);
            float x0 = 0.f, x1 = 0.f, x2 = 0.f, x3 = 0.f;
            float y0 = 0.f, y1 = 0.f, y2 = 0.f, y3 = 0.f;
            #pragma unroll
            for (int i = 0; i < 16; i++) {
                float4 k0 = kr0[i];
                float4 kv1 = kr1[i];
                x0 = fmaf(qr[4 * i    ], k0.x, x0);
                x1 = fmaf(qr[4 * i + 1], k0.y, x1);
                x2 = fmaf(qr[4 * i + 2], k0.z, x2);
                x3 = fmaf(qr[4 * i + 3], k0.w, x3);
                y0 = fmaf(qr[4 * i    ], kv1.x, y0);
                y1 = fmaf(qr[4 * i + 1], kv1.y, y1);
                y2 = fmaf(qr[4 * i + 2], kv1.z, y2);
                y3 = fmaf(qr[4 * i + 3], kv1.w, y3);
            }
            float s0 = (x0 + x1) + (x2 + x3);
            float s1 = two ? (y0 + y1) + (y2 + y3) : -1e30f;

            float mx = fmaxf(s0, s1);
            if (mx > m) {
                float corr = __expf(m - mx);
                m = mx;
                l *= corr;
                #pragma unroll
                for (int d = 0; d < 64; d++) acc[d] *= corr;
            }
            float p0 = __expf(s0 - m);
            float p1 = two ? __expf(s1 - m) : 0.f;
            l += p0 + p1;

            const float4* v0 = (const float4*)(&Vs[kk][0]);
            const float4* v1 = (const float4*)(&Vs[k1][0]);
            #pragma unroll
            for (int i = 0; i < 16; i++) {
                float4 a = v0[i], bb = v1[i];
                acc[4 * i    ] = fmaf(p0, a.x, fmaf(p1, bb.x, acc[4 * i    ]));
                acc[4 * i + 1] = fmaf(p0, a.y, fmaf(p1, bb.y, acc[4 * i + 1]));
                acc[4 * i + 2] = fmaf(p0, a.z, fmaf(p1, bb.z, acc[4 * i + 2]));
                acc[4 * i + 3] = fmaf(p0, a.w, fmaf(p1, bb.w, acc[4 * i + 3]));
            }
        }
        __syncthreads();
    }

    __half2* op = (__half2*)(g_ctx16 + ((size_t)(b * T_ + q)) * D_ + h * DH_);
    if (limit > 0) {
        float invl = 1.f / l;
        #pragma unroll
        for (int d = 0; d < 64; d += 2)
            op[d >> 1] = __floats2half2_rn(acc[d] * invl, acc[d + 1] * invl);
    } else {
        __half2 z = __floats2half2_rn(0.f, 0.f);
        #pragma unroll
        for (int d = 0; d < 64; d += 2) op[d >> 1] = z;
    }
}

// ---------------------------------------------------------------------------
// Classifier
// ---------------------------------------------------------------------------
#define CL_ROWS 16
#define CL_THREADS 192

__global__ __launch_bounds__(CL_THREADS) void classifier_kernel(
    const float* __restrict__ H, const float* __restrict__ Wc,
    const float* __restrict__ bc)
{
    __shared__ float sWc[2 * D_ * C_];
    __shared__ float sred[6 * C_];

    const int tid = threadIdx.x;
    for (int i = tid; i < 2 * D_ * C_; i += CL_THREADS) sWc[i] = Wc[i];
    __syncthreads();

    const int d0 = tid * 4;
    const int row0 = blockIdx.x * CL_ROWS;

    for (int r = 0; r < CL_ROWS; r++) {
        const int row = row0 + r;
        const int t = row & (T_ - 1);
        float facc[C_] = {};
        {
            float4 hv = *(const float4*)(H + (size_t)row * D_ + d0);
            #pragma unroll
            for (int c = 0; c < C_; c++) {
                facc[c] = fmaf(hv.x, sWc[(d0    ) * C_ + c], facc[c]);
                facc[c] = fmaf(hv.y, sWc[(d0 + 1) * C_ + c], facc[c]);
                facc[c] = fmaf(hv.z, sWc[(d0 + 2) * C_ + c], facc[c]);
                facc[c] = fmaf(hv.w, sWc[(d0 + 3) * C_ + c], facc[c]);
            }
            if (t > 0) {
                float4 cv = *(const float4*)(g_c + (size_t)row * D_ + d0);
                #pragma unroll
                for (int c = 0; c < C_; c++) {
                    facc[c] = fmaf(cv.x, sWc[(D_ + d0    ) * C_ + c], facc[c]);
                    facc[c] = fmaf(cv.y, sWc[(D_ + d0 + 1) * C_ + c], facc[c]);
                    facc[c] = fmaf(cv.z, sWc[(D_ + d0 + 2) * C_ + c], facc[c]);
                    facc[c] = fmaf(cv.w, sWc[(D_ + d0 + 3) * C_ + c], facc[c]);
                }
            }
        }
        #pragma unroll
        for (int c = 0; c < C_; c++)
            #pragma unroll
            for (int off = 16; off; off >>= 1)
                facc[c] += __shfl_down_sync(0xffffffff, facc[c], off);
        if ((tid & 31) == 0) {
            int w = tid >> 5;
            #pragma unroll
            for (int c = 0; c < C_; c++) sred[w * C_ + c] = facc[c];
        }
        __syncthreads();
        if (tid < C_) {
            float s = bc[tid];
            #pragma unroll
            for (int w = 0; w < 6; w++) s += sred[w * C_ + tid];
            g_all[(size_t)row * C_ + tid] = s;
        }
        __syncthreads();
    }
}

// ---------------------------------------------------------------------------
__global__ void finalize_kernel(const int* __restrict__ nt, float* __restrict__ out,
                                int out_size)
{
    const int ALL = B_ * T_ * C_;
    const int FIN = B_ * C_;
    int i = blockIdx.x * blockDim.x + threadIdx.x;
    if (out_size >= ALL + FIN) {
        if (i < ALL) out[i] = g_all[i];
        if (i < FIN) {
            int b = i / C_, c = i - b * C_;
            int t = nt[b] - 1;
            out[ALL + i] = g_all[((size_t)(b * T_ + t)) * C_ + c];
        }
    } else if (out_size >= ALL) {
        if (i < ALL) out[i] = g_all[i];
    } else {
        if (i < FIN) {
            int b = i / C_, c = i - b * C_;
            int t = nt[b] - 1;
            out[i] = g_all[((size_t)(b * T_ + t)) * C_ + c];
        }
    }
}

// ---------------------------------------------------------------------------
extern "C" void kernel_launch(void* const* d_in, const int* in_sizes, int n_in,
                              void* d_out, int out_size)
{
    const float* H  = (const float*)d_in[0];
    const float* Wq = (const float*)d_in[1];
    const float* bq = (const float*)d_in[2];
    const float* Wk = (const float*)d_in[3];
    const float* bk = (const float*)d_in[4];
    const float* Wv = (const float*)d_in[5];
    const float* bv = (const float*)d_in[6];
    const float* Wo = (const float*)d_in[7];
    const float* bo = (const float*)d_in[8];
    const float* Wc = (const float*)d_in[9];
    const float* bc = (const float*)d_in[10];
    const int*   nt = (const int*)d_in[11];
    float* out = (float*)d_out;

    float *pq, *pk, *pv, *pc;
    __half *ph16, *pctx16, *pwt16;
    cudaGetSymbolAddress((void**)&pq,     g_q);
    cudaGetSymbolAddress((void**)&pk,     g_k);
    cudaGetSymbolAddress((void**)&pv,     g_v);
    cudaGetSymbolAddress((void**)&pc,     g_c);
    cudaGetSymbolAddress((void**)&ph16,   g_h16);
    cudaGetSymbolAddress((void**)&pctx16, g_ctx16);
    cudaGetSymbolAddress((void**)&pwt16,  g_wt16);

    const int M = B_ * T_;

    // 0) conversions
    const int n4 = M * D_ / 4;
    conv_f2h<<<(n4 + 255) / 256, 256>>>((const float4*)H, (__half2*)ph16, n4);
    transpose4<<<dim3(D_ / 32, D_ / 32, 4), dim3(32, 8)>>>(Wq, Wk, Wv, Wo);

    // 1) fused QKV
    dim3 qkv_grid(D_ / 128, M / 128, 3);
    f16_gemm_bias<<<qkv_grid, 256>>>(ph16, pwt16, bq, pq, bk, pk, bv, pv);

    // 2) attention
    attn_kernel<<<dim3(NH_, B_), 256>>>(nt);

    // 3) out-proj
    dim3 o_grid(D_ / 128, M / 128, 1);
    f16_gemm_bias<<<o_grid, 256>>>(pctx16, pwt16 + (size_t)3 * D_ * D_, bo, pc, bo, pc, bo, pc);

    // 4) classifier + 5) finalize
    classifier_kernel<<<M / CL_ROWS, CL_THREADS>>>(H, Wc, bc);

    const int ALL = B_ * T_ * C_;
    finalize_kernel<<<(ALL + 255) / 256, 256>>>(nt, out, out_size);
}

// round 9
// speedup vs baseline: 2.6614x; 1.4854x over previous
#include <cuda_runtime.h>
#include <cuda_fp16.h>
#include <cstdint>

#define B_ 64
#define T_ 256
#define D_ 768
#define NH_ 12
#define C_ 7
#define DH_ 64

// Scratch (device globals — no allocation allowed)
__device__ float  g_c[B_ * T_ * D_];
__device__ float  g_all[B_ * T_ * C_];
__device__ __half g_h16[B_ * T_ * D_];     // H in half
__device__ __half g_q16[B_ * T_ * D_];
__device__ __half g_k16[B_ * T_ * D_];
__device__ __half g_v16[B_ * T_ * D_];
__device__ __half g_ctx16[B_ * T_ * D_];   // attention output (half)
__device__ __half g_wt16[4 * D_ * D_];     // Wq^T,Wk^T,Wv^T,Wo^T (K-major, half)

// ---------------------------------------------------------------------------
__device__ __forceinline__ uint32_t smem_u32(const void* p) {
    uint32_t a;
    asm("{ .reg .u64 t; cvta.to.shared.u64 t, %1; cvt.u32.u64 %0, t; }" : "=r"(a) : "l"(p));
    return a;
}
__device__ __forceinline__ void cp_async16(uint32_t saddr, const void* src) {
    asm volatile("cp.async.cg.shared.global [%0], [%1], 16;" :: "r"(saddr), "l"(src) : "memory");
}
__device__ __forceinline__ void cp_commit() { asm volatile("cp.async.commit_group;" ::: "memory"); }
__device__ __forceinline__ void cp_wait0()  { asm volatile("cp.async.wait_group 0;" ::: "memory"); }
__device__ __forceinline__ void cp_wait1()  { asm volatile("cp.async.wait_group 1;" ::: "memory"); }

__device__ __forceinline__ void mma_f16(float c[4], const uint32_t a[4], const uint32_t b[2]) {
    asm volatile(
        "mma.sync.aligned.m16n8k16.row.col.f32.f16.f16.f32 "
        "{%0,%1,%2,%3},{%4,%5,%6,%7},{%8,%9},{%0,%1,%2,%3};"
        : "+f"(c[0]), "+f"(c[1]), "+f"(c[2]), "+f"(c[3])
        : "r"(a[0]), "r"(a[1]), "r"(a[2]), "r"(a[3]), "r"(b[0]), "r"(b[1]));
}
__device__ __forceinline__ void ldsm_x4(uint32_t& r0, uint32_t& r1, uint32_t& r2, uint32_t& r3,
                                        uint32_t addr) {
    asm volatile("ldmatrix.sync.aligned.m8n8.x4.shared.b16 {%0,%1,%2,%3}, [%4];"
                 : "=r"(r0), "=r"(r1), "=r"(r2), "=r"(r3) : "r"(addr));
}
__device__ __forceinline__ void ldsm_x4_t(uint32_t& r0, uint32_t& r1, uint32_t& r2, uint32_t& r3,
                                          uint32_t addr) {
    asm volatile("ldmatrix.sync.aligned.m8n8.x4.trans.shared.b16 {%0,%1,%2,%3}, [%4];"
                 : "=r"(r0), "=r"(r1), "=r"(r2), "=r"(r3) : "r"(addr));
}
__device__ __forceinline__ float ex2(float x) {
    float y; asm("ex2.approx.f32 %0, %1;" : "=f"(y) : "f"(x)); return y;
}
__device__ __forceinline__ uint32_t packh2(float lo, float hi) {
    uint32_t r;
    asm("cvt.rn.f16x2.f32 %0, %1, %2;" : "=r"(r) : "f"(hi), "f"(lo));
    return r;
}

// ---------------------------------------------------------------------------
// Conversions
// ---------------------------------------------------------------------------
__global__ void conv_f2h(const float4* __restrict__ src, __half2* __restrict__ dst, int n4)
{
    int i = blockIdx.x * blockDim.x + threadIdx.x;
    if (i < n4) {
        float4 v = src[i];
        dst[2 * i]     = __floats2half2_rn(v.x, v.y);
        dst[2 * i + 1] = __floats2half2_rn(v.z, v.w);
    }
}

// g_wt16[z][n][k] = (half) W_z[k][n]
__global__ void transpose4(const float* __restrict__ Wq, const float* __restrict__ Wk,
                           const float* __restrict__ Wv, const float* __restrict__ Wo)
{
    __shared__ float t[32][33];
    const float* src = (blockIdx.z == 0) ? Wq : (blockIdx.z == 1) ? Wk :
                       (blockIdx.z == 2) ? Wv : Wo;
    __half* dst = g_wt16 + (size_t)blockIdx.z * D_ * D_;
    int x = blockIdx.x * 32 + threadIdx.x;
    int y = blockIdx.y * 32 + threadIdx.y;
    #pragma unroll
    for (int i = 0; i < 32; i += 8)
        t[threadIdx.y + i][threadIdx.x] = src[(size_t)(y + i) * D_ + x];
    __syncthreads();
    x = blockIdx.y * 32 + threadIdx.x;
    y = blockIdx.x * 32 + threadIdx.y;
    #pragma unroll
    for (int i = 0; i < 32; i += 8)
        dst[(size_t)(y + i) * D_ + x] = __float2half(t[threadIdx.x][threadIdx.y + i]);
}

// ---------------------------------------------------------------------------
// FP16 tensor-core GEMM: Out[M,N] = A[M,K] @ WT[N,K]^T + bias[N]   (fp32 accum)
// half_out selects fp16 vs fp32 output.
// ---------------------------------------------------------------------------
#define HST 40
#define HSTAGE (128 * HST * 2 * 2)
#define HBK 32
#define HKT (D_ / HBK)

__global__ __launch_bounds__(256, 2) void f16_gemm_bias(
    const __half* __restrict__ A, const __half* __restrict__ WTbase,
    const float* __restrict__ b0, void* __restrict__ O0,
    const float* __restrict__ b1, void* __restrict__ O1,
    const float* __restrict__ b2, void* __restrict__ O2,
    int half_out)
{
    __shared__ __align__(16) char gsm[2 * HSTAGE];
    const uint32_t sbase = smem_u32(gsm);

    const int tid = threadIdx.x;
    const int bx = blockIdx.x, by = blockIdx.y, bz = blockIdx.z;

    const __half* W    = WTbase + (size_t)bz * D_ * D_;
    const float*  bias = (bz == 0) ? b0 : (bz == 1) ? b1 : b2;
    void*         Cout = (bz == 0) ? O0 : (bz == 1) ? O1 : O2;

    const int warp = tid >> 5;
    const int lane = tid & 31;
    const int gid = lane >> 2;
    const int tig = lane & 3;
    const int m0 = (warp & 3) * 32;
    const int n0 = (warp >> 2) * 64;

    const __half* Ag = A + (size_t)(by * 128) * D_;
    const __half* Wg = W + (size_t)(bx * 128) * D_;

    const int frow = tid >> 1;
    const int g0   = (tid & 1) * 2;

    const int a_r = ((lane >> 3) & 1) * 8 + (lane & 7);
    const int a_c = (lane >> 4) * 8;
    const int b_r = (lane >> 4) * 8 + (lane & 7);
    const int b_c = ((lane >> 3) & 1) * 8;
    const uint32_t aoff0 = ((m0 + a_r) * HST + a_c) * 2;
    const uint32_t boff0 = 128 * HST * 2 + ((n0 + b_r) * HST + b_c) * 2;

    float acc[2][8][4] = {};

    #define HFILL(buf, kt) do {                                                   \
        const uint32_t sa = sbase + (buf) * HSTAGE;                               \
        const uint32_t sb = sa + 128 * HST * 2;                                   \
        const int kb = (kt) * HBK;                                                \
        _Pragma("unroll")                                                         \
        for (int g = g0; g < g0 + 2; g++) {                                       \
            cp_async16(sa + frow * (HST * 2) + g * 16,                            \
                       Ag + (size_t)frow * D_ + kb + g * 8);                      \
            cp_async16(sb + frow * (HST * 2) + g * 16,                            \
                       Wg + (size_t)frow * D_ + kb + g * 8);                      \
        }                                                                         \
    } while (0)

    HFILL(0, 0);
    cp_commit();

    for (int kt = 0; kt < HKT; kt++) {
        const int buf = kt & 1;
        if (kt + 1 < HKT) HFILL(buf ^ 1, kt + 1);
        cp_commit();
        cp_wait1();
        __syncthreads();

        const uint32_t stage = sbase + buf * HSTAGE;

        #pragma unroll
        for (int kk = 0; kk < HBK; kk += 16) {
            uint32_t a[2][4], b[8][2];
            ldsm_x4(a[0][0], a[0][1], a[0][2], a[0][3], stage + aoff0 + kk * 2);
            ldsm_x4(a[1][0], a[1][1], a[1][2], a[1][3], stage + aoff0 + 16 * HST * 2 + kk * 2);
            #pragma unroll
            for (int jp = 0; jp < 4; jp++)
                ldsm_x4(b[2 * jp][0], b[2 * jp][1], b[2 * jp + 1][0], b[2 * jp + 1][1],
                        stage + boff0 + jp * 16 * HST * 2 + kk * 2);
            #pragma unroll
            for (int mt = 0; mt < 2; mt++)
                #pragma unroll
                for (int nt = 0; nt < 8; nt++)
                    mma_f16(acc[mt][nt], a[mt], b[nt]);
        }
        __syncthreads();
    }
    cp_wait0();

    #pragma unroll
    for (int mt = 0; mt < 2; mt++) {
        #pragma unroll
        for (int nt = 0; nt < 8; nt++) {
            int row = by * 128 + m0 + mt * 16 + gid;
            int col = bx * 128 + n0 + nt * 8 + tig * 2;
            float bx0 = bias[col], bx1 = bias[col + 1];
            float v00 = acc[mt][nt][0] + bx0, v01 = acc[mt][nt][1] + bx1;
            float v10 = acc[mt][nt][2] + bx0, v11 = acc[mt][nt][3] + bx1;
            if (half_out) {
                __half* Ch = (__half*)Cout;
                *(__half2*)(Ch + (size_t)row * D_ + col)       = __floats2half2_rn(v00, v01);
                *(__half2*)(Ch + (size_t)(row + 8) * D_ + col) = __floats2half2_rn(v10, v11);
            } else {
                float* Cf = (float*)Cout;
                *(float2*)(Cf + (size_t)row * D_ + col)       = make_float2(v00, v01);
                *(float2*)(Cf + (size_t)(row + 8) * D_ + col) = make_float2(v10, v11);
            }
        }
    }
}

// ---------------------------------------------------------------------------
// Flash attention (tensor cores, m16n8k16): block = 4 warps, 64-query tile.
// grid (NH, B, 4). K/V chunks of 64 keys staged in smem (half, stride 72).
// Per warp: 16 queries. Online softmax in fragments.
// ---------------------------------------------------------------------------
__global__ __launch_bounds__(128) void attn_mma(const int* __restrict__ num_turns)
{
    const int h = blockIdx.x;
    const int b = blockIdx.y;
    const int qbase = blockIdx.z * 64;
    const int tid = threadIdx.x;
    const int w = tid >> 5;
    const int lane = tid & 31;
    const int gid = lane >> 2, tig = lane & 3;
    const int id = lane >> 3;

    __shared__ __half Qs[64][72];
    __shared__ __half Ks[64][72];
    __shared__ __half Vs[64][72];

    const int ntb = num_turns[b];
    int maxlim = qbase + 63; if (ntb < maxlim) maxlim = ntb;
    const int nchunks = (maxlim + 63) >> 6;

    // stage Q tile (64 x 64 halves)
    {
        int row = tid >> 1, c0 = (tid & 1) * 32;
        const uint4* src = (const uint4*)(g_q16 + ((size_t)(b * T_) + qbase + row) * D_ + h * DH_ + c0);
        uint4* dst = (uint4*)&Qs[row][c0];
        #pragma unroll
        for (int i = 0; i < 4; i++) dst[i] = src[i];
    }
    __syncthreads();

    // Q fragments (A of m16n8k16), 4 k-steps
    uint32_t aQ[4][4];
    #pragma unroll
    for (int ks = 0; ks < 4; ks++) {
        uint32_t addr = smem_u32(&Qs[w * 16 + (id & 1) * 8 + (lane & 7)][ks * 16 + (id >> 1) * 8]);
        ldsm_x4(aQ[ks][0], aQ[ks][1], aQ[ks][2], aQ[ks][3], addr);
    }

    const int qg0 = qbase + w * 16 + gid;         // row 0 global query
    const int lim0 = (qg0 < ntb) ? qg0 : ntb;     // valid keys row0
    const int lim1 = (qg0 + 8 < ntb) ? (qg0 + 8) : ntb;
    const float Cc = 0.18033688f;                 // 0.125 * log2(e)

    float m0 = -1e30f, m1 = -1e30f, l0 = 0.f, l1 = 0.f;
    float oacc[8][4] = {};

    for (int ch = 0; ch < nchunks; ch++) {
        const int kbase = ch * 64;
        {
            int row = tid >> 1, c0 = (tid & 1) * 32;
            const uint4* ksrc = (const uint4*)(g_k16 + ((size_t)(b * T_) + kbase + row) * D_ + h * DH_ + c0);
            const uint4* vsrc = (const uint4*)(g_v16 + ((size_t)(b * T_) + kbase + row) * D_ + h * DH_ + c0);
            uint4* kd = (uint4*)&Ks[row][c0];
            uint4* vd = (uint4*)&Vs[row][c0];
            #pragma unroll
            for (int i = 0; i < 4; i++) { kd[i] = ksrc[i]; vd[i] = vsrc[i]; }
        }
        __syncthreads();

        // S = Q @ K^T  (16 x 64 per warp)
        float sacc[8][4] = {};
        #pragma unroll
        for (int ks = 0; ks < 4; ks++) {
            uint32_t bk[8][2];
            #pragma unroll
            for (int j = 0; j < 4; j++) {
                uint32_t addr = smem_u32(&Ks[j * 16 + (id >> 1) * 8 + (lane & 7)][ks * 16 + (id & 1) * 8]);
                ldsm_x4(bk[2 * j][0], bk[2 * j][1], bk[2 * j + 1][0], bk[2 * j + 1][1], addr);
            }
            #pragma unroll
            for (int j = 0; j < 8; j++)
                mma_f16(sacc[j], aQ[ks], bk[j]);
        }

        // mask invalid keys
        #pragma unroll
        for (int j = 0; j < 8; j++) {
            int c0 = kbase + j * 8 + tig * 2;
            if (c0     >= lim0) sacc[j][0] = -1e30f;
            if (c0 + 1 >= lim0) sacc[j][1] = -1e30f;
            if (c0     >= lim1) sacc[j][2] = -1e30f;
            if (c0 + 1 >= lim1) sacc[j][3] = -1e30f;
        }
        // row max (thread-local then quad reduce)
        float mx0 = -1e30f, mx1 = -1e30f;
        #pragma unroll
        for (int j = 0; j < 8; j++) {
            mx0 = fmaxf(mx0, fmaxf(sacc[j][0], sacc[j][1]));
            mx1 = fmaxf(mx1, fmaxf(sacc[j][2], sacc[j][3]));
        }
        mx0 = fmaxf(mx0, __shfl_xor_sync(0xffffffff, mx0, 1));
        mx0 = fmaxf(mx0, __shfl_xor_sync(0xffffffff, mx0, 2));
        mx1 = fmaxf(mx1, __shfl_xor_sync(0xffffffff, mx1, 1));
        mx1 = fmaxf(mx1, __shfl_xor_sync(0xffffffff, mx1, 2));

        float mn0 = fmaxf(m0, mx0), mn1 = fmaxf(m1, mx1);
        float cr0 = ex2((m0 - mn0) * Cc), cr1 = ex2((m1 - mn1) * Cc);
        m0 = mn0; m1 = mn1;

        // p = exp2((s - m)*C); pack into A-fragments of P
        uint32_t pa[4][4];
        float rs0 = 0.f, rs1 = 0.f;
        #pragma unroll
        for (int j = 0; j < 8; j++) {
            float p0 = ex2((sacc[j][0] - m0) * Cc);
            float p1 = ex2((sacc[j][1] - m0) * Cc);
            float p2 = ex2((sacc[j][2] - m1) * Cc);
            float p3 = ex2((sacc[j][3] - m1) * Cc);
            rs0 += p0 + p1; rs1 += p2 + p3;
            uint32_t h01 = packh2(p0, p1), h23 = packh2(p2, p3);
            if ((j & 1) == 0) { pa[j >> 1][0] = h01; pa[j >> 1][1] = h23; }
            else              { pa[j >> 1][2] = h01; pa[j >> 1][3] = h23; }
        }
        l0 = l0 * cr0 + rs0;
        l1 = l1 * cr1 + rs1;
        #pragma unroll
        for (int j = 0; j < 8; j++) {
            oacc[j][0] *= cr0; oacc[j][1] *= cr0;
            oacc[j][2] *= cr1; oacc[j][3] *= cr1;
        }

        // O += P @ V
        #pragma unroll
        for (int ks2 = 0; ks2 < 4; ks2++) {
            uint32_t bv[8][2];
            #pragma unroll
            for (int j = 0; j < 4; j++) {
                uint32_t addr = smem_u32(&Vs[ks2 * 16 + (id & 1) * 8 + (lane & 7)][j * 16 + (id >> 1) * 8]);
                ldsm_x4_t(bv[2 * j][0], bv[2 * j][1], bv[2 * j + 1][0], bv[2 * j + 1][1], addr);
            }
            #pragma unroll
            for (int j = 0; j < 8; j++)
                mma_f16(oacc[j], pa[ks2], bv[j]);
        }
        __syncthreads();
    }

    // reduce l across quad, normalize, store
    l0 += __shfl_xor_sync(0xffffffff, l0, 1);
    l0 += __shfl_xor_sync(0xffffffff, l0, 2);
    l1 += __shfl_xor_sync(0xffffffff, l1, 1);
    l1 += __shfl_xor_sync(0xffffffff, l1, 2);
    float inv0 = (lim0 > 0) ? 1.f / l0 : 0.f;
    float inv1 = (lim1 > 0) ? 1.f / l1 : 0.f;

    size_t base0 = ((size_t)(b * T_) + qg0) * D_ + h * DH_;
    size_t base1 = base0 + (size_t)8 * D_;
    #pragma unroll
    for (int j = 0; j < 8; j++) {
        int col = j * 8 + tig * 2;
        *(__half2*)(g_ctx16 + base0 + col) = __floats2half2_rn(oacc[j][0] * inv0, oacc[j][1] * inv0);
        *(__half2*)(g_ctx16 + base1 + col) = __floats2half2_rn(oacc[j][2] * inv1, oacc[j][3] * inv1);
    }
}

// ---------------------------------------------------------------------------
// Classifier
// ---------------------------------------------------------------------------
#define CL_ROWS 16
#define CL_THREADS 192

__global__ __launch_bounds__(CL_THREADS) void classifier_kernel(
    const float* __restrict__ H, const float* __restrict__ Wc,
    const float* __restrict__ bc)
{
    __shared__ float sWc[2 * D_ * C_];
    __shared__ float sred[6 * C_];

    const int tid = threadIdx.x;
    for (int i = tid; i < 2 * D_ * C_; i += CL_THREADS) sWc[i] = Wc[i];
    __syncthreads();

    const int d0 = tid * 4;
    const int row0 = blockIdx.x * CL_ROWS;

    for (int r = 0; r < CL_ROWS; r++) {
        const int row = row0 + r;
        const int t = row & (T_ - 1);
        float facc[C_] = {};
        {
            float4 hv = *(const float4*)(H + (size_t)row * D_ + d0);
            #pragma unroll
            for (int c = 0; c < C_; c++) {
                facc[c] = fmaf(hv.x, sWc[(d0    ) * C_ + c], facc[c]);
                facc[c] = fmaf(hv.y, sWc[(d0 + 1) * C_ + c], facc[c]);
                facc[c] = fmaf(hv.z, sWc[(d0 + 2) * C_ + c], facc[c]);
                facc[c] = fmaf(hv.w, sWc[(d0 + 3) * C_ + c], facc[c]);
            }
            if (t > 0) {
                float4 cv = *(const float4*)(g_c + (size_t)row * D_ + d0);
                #pragma unroll
                for (int c = 0; c < C_; c++) {
                    facc[c] = fmaf(cv.x, sWc[(D_ + d0    ) * C_ + c], facc[c]);
                    facc[c] = fmaf(cv.y, sWc[(D_ + d0 + 1) * C_ + c], facc[c]);
                    facc[c] = fmaf(cv.z, sWc[(D_ + d0 + 2) * C_ + c], facc[c]);
                    facc[c] = fmaf(cv.w, sWc[(D_ + d0 + 3) * C_ + c], facc[c]);
                }
            }
        }
        #pragma unroll
        for (int c = 0; c < C_; c++)
            #pragma unroll
            for (int off = 16; off; off >>= 1)
                facc[c] += __shfl_down_sync(0xffffffff, facc[c], off);
        if ((tid & 31) == 0) {
            int w = tid >> 5;
            #pragma unroll
            for (int c = 0; c < C_; c++) sred[w * C_ + c] = facc[c];
        }
        __syncthreads();
        if (tid < C_) {
            float s = bc[tid];
            #pragma unroll
            for (int w = 0; w < 6; w++) s += sred[w * C_ + tid];
            g_all[(size_t)row * C_ + tid] = s;
        }
        __syncthreads();
    }
}

// ---------------------------------------------------------------------------
__global__ void finalize_kernel(const int* __restrict__ nt, float* __restrict__ out,
                                int out_size)
{
    const int ALL = B_ * T_ * C_;
    const int FIN = B_ * C_;
    int i = blockIdx.x * blockDim.x + threadIdx.x;
    if (out_size >= ALL + FIN) {
        if (i < ALL) out[i] = g_all[i];
        if (i < FIN) {
            int b = i / C_, c = i - b * C_;
            int t = nt[b] - 1;
            out[ALL + i] = g_all[((size_t)(b * T_ + t)) * C_ + c];
        }
    } else if (out_size >= ALL) {
        if (i < ALL) out[i] = g_all[i];
    } else {
        if (i < FIN) {
            int b = i / C_, c = i - b * C_;
            int t = nt[b] - 1;
            out[i] = g_all[((size_t)(b * T_ + t)) * C_ + c];
        }
    }
}

// ---------------------------------------------------------------------------
extern "C" void kernel_launch(void* const* d_in, const int* in_sizes, int n_in,
                              void* d_out, int out_size)
{
    const float* H  = (const float*)d_in[0];
    const float* Wq = (const float*)d_in[1];
    const float* bq = (const float*)d_in[2];
    const float* Wk = (const float*)d_in[3];
    const float* bk = (const float*)d_in[4];
    const float* Wv = (const float*)d_in[5];
    const float* bv = (const float*)d_in[6];
    const float* Wo = (const float*)d_in[7];
    const float* bo = (const float*)d_in[8];
    const float* Wc = (const float*)d_in[9];
    const float* bc = (const float*)d_in[10];
    const int*   nt = (const int*)d_in[11];
    float* out = (float*)d_out;

    float *pc;
    __half *ph16, *pq16, *pk16, *pv16, *pctx16, *pwt16;
    cudaGetSymbolAddress((void**)&pc,     g_c);
    cudaGetSymbolAddress((void**)&ph16,   g_h16);
    cudaGetSymbolAddress((void**)&pq16,   g_q16);
    cudaGetSymbolAddress((void**)&pk16,   g_k16);
    cudaGetSymbolAddress((void**)&pv16,   g_v16);
    cudaGetSymbolAddress((void**)&pctx16, g_ctx16);
    cudaGetSymbolAddress((void**)&pwt16,  g_wt16);

    const int M = B_ * T_;

    // 0) conversions
    const int n4 = M * D_ / 4;
    conv_f2h<<<(n4 + 255) / 256, 256>>>((const float4*)H, (__half2*)ph16, n4);
    transpose4<<<dim3(D_ / 32, D_ / 32, 4), dim3(32, 8)>>>(Wq, Wk, Wv, Wo);

    // 1) fused QKV -> half outputs
    dim3 qkv_grid(D_ / 128, M / 128, 3);
    f16_gemm_bias<<<qkv_grid, 256>>>(ph16, pwt16, bq, pq16, bk, pk16, bv, pv16, 1);

    // 2) flash attention (tensor cores)
    attn_mma<<<dim3(NH_, B_, 4), 128>>>(nt);

    // 3) out-proj -> fp32 output
    dim3 o_grid(D_ / 128, M / 128, 1);
    f16_gemm_bias<<<o_grid, 256>>>(pctx16, pwt16 + (size_t)3 * D_ * D_, bo, pc, bo, pc, bo, pc, 0);

    // 4) classifier + 5) finalize
    classifier_kernel<<<M / CL_ROWS, CL_THREADS>>>(H, Wc, bc);

    const int ALL = B_ * T_ * C_;
    finalize_kernel<<<(ALL + 255) / 256, 256>>>(nt, out, out_size);
}

// round 13
// speedup vs baseline: 2.8734x; 1.0796x over previous
#include <cuda_runtime.h>
#include <cuda_fp16.h>
#include <cstdint>

#define B_ 64
#define T_ 256
#define D_ 768
#define NH_ 12
#define C_ 7
#define DH_ 64

// Scratch (device globals — no allocation allowed)
__device__ float  g_all[B_ * T_ * C_];
__device__ float  g_cls[2 * 7 * D_];       // [WcTopT (7x768)][WfusedT (7x768)]
__device__ float  g_bo7[8];
__device__ __half g_h16[B_ * T_ * D_];     // H in half
__device__ __half g_q16[B_ * T_ * D_];
__device__ __half g_k16[B_ * T_ * D_];
__device__ __half g_v16[B_ * T_ * D_];
__device__ __half g_ctx16[B_ * T_ * D_];   // attention output (half)
__device__ __half g_wt16[3 * D_ * D_];     // Wq^T,Wk^T,Wv^T (K-major, half)

// ---------------------------------------------------------------------------
__device__ __forceinline__ uint32_t smem_u32(const void* p) {
    uint32_t a;
    asm("{ .reg .u64 t; cvta.to.shared.u64 t, %1; cvt.u32.u64 %0, t; }" : "=r"(a) : "l"(p));
    return a;
}
__device__ __forceinline__ void cp_async16(uint32_t saddr, const void* src) {
    asm volatile("cp.async.cg.shared.global [%0], [%1], 16;" :: "r"(saddr), "l"(src) : "memory");
}
__device__ __forceinline__ void cp_commit() { asm volatile("cp.async.commit_group;" ::: "memory"); }
__device__ __forceinline__ void cp_wait0()  { asm volatile("cp.async.wait_group 0;" ::: "memory"); }
__device__ __forceinline__ void cp_wait1()  { asm volatile("cp.async.wait_group 1;" ::: "memory"); }

__device__ __forceinline__ void mma_f16(float c[4], const uint32_t a[4], const uint32_t b[2]) {
    asm volatile(
        "mma.sync.aligned.m16n8k16.row.col.f32.f16.f16.f32 "
        "{%0,%1,%2,%3},{%4,%5,%6,%7},{%8,%9},{%0,%1,%2,%3};"
        : "+f"(c[0]), "+f"(c[1]), "+f"(c[2]), "+f"(c[3])
        : "r"(a[0]), "r"(a[1]), "r"(a[2]), "r"(a[3]), "r"(b[0]), "r"(b[1]));
}
__device__ __forceinline__ void ldsm_x4(uint32_t& r0, uint32_t& r1, uint32_t& r2, uint32_t& r3,
                                        uint32_t addr) {
    asm volatile("ldmatrix.sync.aligned.m8n8.x4.shared.b16 {%0,%1,%2,%3}, [%4];"
                 : "=r"(r0), "=r"(r1), "=r"(r2), "=r"(r3) : "r"(addr));
}
__device__ __forceinline__ void ldsm_x4_t(uint32_t& r0, uint32_t& r1, uint32_t& r2, uint32_t& r3,
                                          uint32_t addr) {
    asm volatile("ldmatrix.sync.aligned.m8n8.x4.trans.shared.b16 {%0,%1,%2,%3}, [%4];"
                 : "=r"(r0), "=r"(r1), "=r"(r2), "=r"(r3) : "r"(addr));
}
__device__ __forceinline__ float ex2(float x) {
    float y; asm("ex2.approx.f32 %0, %1;" : "=f"(y) : "f"(x)); return y;
}
__device__ __forceinline__ uint32_t packh2(float lo, float hi) {
    uint32_t r;
    asm("cvt.rn.f16x2.f32 %0, %1, %2;" : "=r"(r) : "f"(hi), "f"(lo));
    return r;
}

// ---------------------------------------------------------------------------
// Conversions
// ---------------------------------------------------------------------------
__global__ void conv_f2h(const float4* __restrict__ src, __half2* __restrict__ dst, int n4)
{
    int i = blockIdx.x * blockDim.x + threadIdx.x;
    if (i < n4) {
        float4 v = src[i];
        dst[2 * i]     = __floats2half2_rn(v.x, v.y);
        dst[2 * i + 1] = __floats2half2_rn(v.z, v.w);
    }
}

// g_wt16[z][n][k] = (half) W_z[k][n]   (z = 0,1,2 -> Wq,Wk,Wv)
__global__ void transpose3(const float* __restrict__ Wq, const float* __restrict__ Wk,
                           const float* __restrict__ Wv)
{
    __shared__ float t[32][33];
    const float* src = (blockIdx.z == 0) ? Wq : (blockIdx.z == 1) ? Wk : Wv;
    __half* dst = g_wt16 + (size_t)blockIdx.z * D_ * D_;
    int x = blockIdx.x * 32 + threadIdx.x;
    int y = blockIdx.y * 32 + threadIdx.y;
    #pragma unroll
    for (int i = 0; i < 32; i += 8)
        t[threadIdx.y + i][threadIdx.x] = src[(size_t)(y + i) * D_ + x];
    __syncthreads();
    x = blockIdx.y * 32 + threadIdx.x;
    y = blockIdx.x * 32 + threadIdx.y;
    #pragma unroll
    for (int i = 0; i < 32; i += 8)
        dst[(size_t)(y + i) * D_ + x] = __float2half(t[threadIdx.x][threadIdx.y + i]);
}

// ---------------------------------------------------------------------------
// Prep: WcTopT[c][d] = Wc[d][c]; WfusedT[c][d] = sum_n Wo[d][n]*Wc[D+n][c];
//       bo7[c] = sum_n bo[n]*Wc[D+n][c]
// grid = 8 blocks x 128 threads. Wc_bot rows are contiguous: Wc[5376 + n*7 + c].
// ---------------------------------------------------------------------------
__global__ void fuse_prep(const float* __restrict__ Wo, const float* __restrict__ Wc,
                          const float* __restrict__ bo)
{
    __shared__ float sWb[D_ * C_];   // Wc_bot, 21504 B
    const int tid = threadIdx.x;
    const int blk = blockIdx.x;
    if (blk < 6) {
        for (int i = tid; i < D_ * C_; i += 128) sWb[i] = Wc[D_ * C_ + i];
        __syncthreads();
        const int d = blk * 128 + tid;
        const float* wo = Wo + (size_t)d * D_;
        float acc[C_] = {};
        for (int n = 0; n < D_; n++) {
            float w = wo[n];
            #pragma unroll
            for (int c = 0; c < C_; c++) acc[c] = fmaf(w, sWb[n * C_ + c], acc[c]);
        }
        #pragma unroll
        for (int c = 0; c < C_; c++) g_cls[C_ * D_ + c * D_ + d] = acc[c];
    } else if (blk == 6) {
        for (int i = tid; i < D_ * C_; i += 128) {
            int c = i / D_, d = i - c * D_;
            g_cls[i] = Wc[d * C_ + c];
        }
    } else {
        if (tid < C_) {
            float a = 0.f;
            for (int n = 0; n < D_; n++) a = fmaf(bo[n], Wc[D_ * C_ + n * C_ + tid], a);
            g_bo7[tid] = a;
        }
    }
}

// ---------------------------------------------------------------------------
// FP16 tensor-core GEMM: Out[M,N] = A[M,K] @ WT[N,K]^T + bias[N] -> half out
// ---------------------------------------------------------------------------
#define HST 40
#define HSTAGE (128 * HST * 2 * 2)
#define HBK 32
#define HKT (D_ / HBK)

__global__ __launch_bounds__(256, 2) void f16_gemm_bias(
    const __half* __restrict__ A, const __half* __restrict__ WTbase,
    const float* __restrict__ b0, __half* __restrict__ O0,
    const float* __restrict__ b1, __half* __restrict__ O1,
    const float* __restrict__ b2, __half* __restrict__ O2)
{
    __shared__ __align__(16) char gsm[2 * HSTAGE];
    const uint32_t sbase = smem_u32(gsm);

    const int tid = threadIdx.x;
    const int bx = blockIdx.x, by = blockIdx.y, bz = blockIdx.z;

    const __half* W    = WTbase + (size_t)bz * D_ * D_;
    const float*  bias = (bz == 0) ? b0 : (bz == 1) ? b1 : b2;
    __half*       Cout = (bz == 0) ? O0 : (bz == 1) ? O1 : O2;

    const int warp = tid >> 5;
    const int lane = tid & 31;
    const int gid = lane >> 2;
    const int tig = lane & 3;
    const int m0 = (warp & 3) * 32;
    const int n0 = (warp >> 2) * 64;

    const __half* Ag = A + (size_t)(by * 128) * D_;
    const __half* Wg = W + (size_t)(bx * 128) * D_;

    const int frow = tid >> 1;
    const int g0   = (tid & 1) * 2;

    const int a_r = ((lane >> 3) & 1) * 8 + (lane & 7);
    const int a_c = (lane >> 4) * 8;
    const int b_r = (lane >> 4) * 8 + (lane & 7);
    const int b_c = ((lane >> 3) & 1) * 8;
    const uint32_t aoff0 = ((m0 + a_r) * HST + a_c) * 2;
    const uint32_t boff0 = 128 * HST * 2 + ((n0 + b_r) * HST + b_c) * 2;

    float acc[2][8][4] = {};

    #define HFILL(buf, kt) do {                                                   \
        const uint32_t sa = sbase + (buf) * HSTAGE;                               \
        const uint32_t sb = sa + 128 * HST * 2;                                   \
        const int kb = (kt) * HBK;                                                \
        _Pragma("unroll")                                                         \
        for (int g = g0; g < g0 + 2; g++) {                                       \
            cp_async16(sa + frow * (HST * 2) + g * 16,                            \
                       Ag + (size_t)frow * D_ + kb + g * 8);                      \
            cp_async16(sb + frow * (HST * 2) + g * 16,                            \
                       Wg + (size_t)frow * D_ + kb + g * 8);                      \
        }                                                                         \
    } while (0)

    HFILL(0, 0);
    cp_commit();

    for (int kt = 0; kt < HKT; kt++) {
        const int buf = kt & 1;
        if (kt + 1 < HKT) HFILL(buf ^ 1, kt + 1);
        cp_commit();
        cp_wait1();
        __syncthreads();

        const uint32_t stage = sbase + buf * HSTAGE;

        #pragma unroll
        for (int kk = 0; kk < HBK; kk += 16) {
            uint32_t a[2][4], b[8][2];
            ldsm_x4(a[0][0], a[0][1], a[0][2], a[0][3], stage + aoff0 + kk * 2);
            ldsm_x4(a[1][0], a[1][1], a[1][2], a[1][3], stage + aoff0 + 16 * HST * 2 + kk * 2);
            #pragma unroll
            for (int jp = 0; jp < 4; jp++)
                ldsm_x4(b[2 * jp][0], b[2 * jp][1], b[2 * jp + 1][0], b[2 * jp + 1][1],
                        stage + boff0 + jp * 16 * HST * 2 + kk * 2);
            #pragma unroll
            for (int mt = 0; mt < 2; mt++)
                #pragma unroll
                for (int nt = 0; nt < 8; nt++)
                    mma_f16(acc[mt][nt], a[mt], b[nt]);
        }
        __syncthreads();
    }
    cp_wait0();

    #pragma unroll
    for (int mt = 0; mt < 2; mt++) {
        #pragma unroll
        for (int nt = 0; nt < 8; nt++) {
            int row = by * 128 + m0 + mt * 16 + gid;
            int col = bx * 128 + n0 + nt * 8 + tig * 2;
            float bx0 = bias[col], bx1 = bias[col + 1];
            *(__half2*)(Cout + (size_t)row * D_ + col) =
                __floats2half2_rn(acc[mt][nt][0] + bx0, acc[mt][nt][1] + bx1);
            *(__half2*)(Cout + (size_t)(row + 8) * D_ + col) =
                __floats2half2_rn(acc[mt][nt][2] + bx0, acc[mt][nt][3] + bx1);
        }
    }
}

// ---------------------------------------------------------------------------
// Flash attention (tensor cores, m16n8k16): block = 4 warps, 64-query tile.
// ---------------------------------------------------------------------------
__global__ __launch_bounds__(128) void attn_mma(const int* __restrict__ num_turns)
{
    const int h = blockIdx.x;
    const int b = blockIdx.y;
    const int qbase = blockIdx.z * 64;
    const int tid = threadIdx.x;
    const int w = tid >> 5;
    const int lane = tid & 31;
    const int gid = lane >> 2, tig = lane & 3;
    const int id = lane >> 3;

    __shared__ __half Qs[64][72];
    __shared__ __half Ks[64][72];
    __shared__ __half Vs[64][72];

    const int ntb = num_turns[b];
    int maxlim = qbase + 63; if (ntb < maxlim) maxlim = ntb;
    const int nchunks = (maxlim + 63) >> 6;

    {
        int row = tid >> 1, c0 = (tid & 1) * 32;
        const uint4* src = (const uint4*)(g_q16 + ((size_t)(b * T_) + qbase + row) * D_ + h * DH_ + c0);
        uint4* dst = (uint4*)&Qs[row][c0];
        #pragma unroll
        for (int i = 0; i < 4; i++) dst[i] = src[i];
    }
    __syncthreads();

    uint32_t aQ[4][4];
    #pragma unroll
    for (int ks = 0; ks < 4; ks++) {
        uint32_t addr = smem_u32(&Qs[w * 16 + (id & 1) * 8 + (lane & 7)][ks * 16 + (id >> 1) * 8]);
        ldsm_x4(aQ[ks][0], aQ[ks][1], aQ[ks][2], aQ[ks][3], addr);
    }

    const int qg0 = qbase + w * 16 + gid;
    const int lim0 = (qg0 < ntb) ? qg0 : ntb;
    const int lim1 = (qg0 + 8 < ntb) ? (qg0 + 8) : ntb;
    const float Cc = 0.18033688f;   // 0.125 * log2(e)

    float m0 = -1e30f, m1 = -1e30f, l0 = 0.f, l1 = 0.f;
    float oacc[8][4] = {};

    for (int ch = 0; ch < nchunks; ch++) {
        const int kbase = ch * 64;
        {
            int row = tid >> 1, c0 = (tid & 1) * 32;
            const uint4* ksrc = (const uint4*)(g_k16 + ((size_t)(b * T_) + kbase + row) * D_ + h * DH_ + c0);
            const uint4* vsrc = (const uint4*)(g_v16 + ((size_t)(b * T_) + kbase + row) * D_ + h * DH_ + c0);
            uint4* kd = (uint4*)&Ks[row][c0];
            uint4* vd = (uint4*)&Vs[row][c0];
            #pragma unroll
            for (int i = 0; i < 4; i++) { kd[i] = ksrc[i]; vd[i] = vsrc[i]; }
        }
        __syncthreads();

        float sacc[8][4] = {};
        #pragma unroll
        for (int ks = 0; ks < 4; ks++) {
            uint32_t bk[8][2];
            #pragma unroll
            for (int j = 0; j < 4; j++) {
                uint32_t addr = smem_u32(&Ks[j * 16 + (id >> 1) * 8 + (lane & 7)][ks * 16 + (id & 1) * 8]);
                ldsm_x4(bk[2 * j][0], bk[2 * j][1], bk[2 * j + 1][0], bk[2 * j + 1][1], addr);
            }
            #pragma unroll
            for (int j = 0; j < 8; j++)
                mma_f16(sacc[j], aQ[ks], bk[j]);
        }

        #pragma unroll
        for (int j = 0; j < 8; j++) {
            int c0 = kbase + j * 8 + tig * 2;
            if (c0     >= lim0) sacc[j][0] = -1e30f;
            if (c0 + 1 >= lim0) sacc[j][1] = -1e30f;
            if (c0     >= lim1) sacc[j][2] = -1e30f;
            if (c0 + 1 >= lim1) sacc[j][3] = -1e30f;
        }
        float mx0 = -1e30f, mx1 = -1e30f;
        #pragma unroll
        for (int j = 0; j < 8; j++) {
            mx0 = fmaxf(mx0, fmaxf(sacc[j][0], sacc[j][1]));
            mx1 = fmaxf(mx1, fmaxf(sacc[j][2], sacc[j][3]));
        }
        mx0 = fmaxf(mx0, __shfl_xor_sync(0xffffffff, mx0, 1));
        mx0 = fmaxf(mx0, __shfl_xor_sync(0xffffffff, mx0, 2));
        mx1 = fmaxf(mx1, __shfl_xor_sync(0xffffffff, mx1, 1));
        mx1 = fmaxf(mx1, __shfl_xor_sync(0xffffffff, mx1, 2));

        float mn0 = fmaxf(m0, mx0), mn1 = fmaxf(m1, mx1);
        float cr0 = ex2((m0 - mn0) * Cc), cr1 = ex2((m1 - mn1) * Cc);
        m0 = mn0; m1 = mn1;

        uint32_t pa[4][4];
        float rs0 = 0.f, rs1 = 0.f;
        #pragma unroll
        for (int j = 0; j < 8; j++) {
            float p0 = ex2((sacc[j][0] - m0) * Cc);
            float p1 = ex2((sacc[j][1] - m0) * Cc);
            float p2 = ex2((sacc[j][2] - m1) * Cc);
            float p3 = ex2((sacc[j][3] - m1) * Cc);
            rs0 += p0 + p1; rs1 += p2 + p3;
            uint32_t h01 = packh2(p0, p1), h23 = packh2(p2, p3);
            if ((j & 1) == 0) { pa[j >> 1][0] = h01; pa[j >> 1][1] = h23; }
            else              { pa[j >> 1][2] = h01; pa[j >> 1][3] = h23; }
        }
        l0 = l0 * cr0 + rs0;
        l1 = l1 * cr1 + rs1;
        #pragma unroll
        for (int j = 0; j < 8; j++) {
            oacc[j][0] *= cr0; oacc[j][1] *= cr0;
            oacc[j][2] *= cr1; oacc[j][3] *= cr1;
        }

        #pragma unroll
        for (int ks2 = 0; ks2 < 4; ks2++) {
            uint32_t bv[8][2];
            #pragma unroll
            for (int j = 0; j < 4; j++) {
                uint32_t addr = smem_u32(&Vs[ks2 * 16 + (id & 1) * 8 + (lane & 7)][j * 16 + (id >> 1) * 8]);
                ldsm_x4_t(bv[2 * j][0], bv[2 * j][1], bv[2 * j + 1][0], bv[2 * j + 1][1], addr);
            }
            #pragma unroll
            for (int j = 0; j < 8; j++)
                mma_f16(oacc[j], pa[ks2], bv[j]);
        }
        __syncthreads();
    }

    l0 += __shfl_xor_sync(0xffffffff, l0, 1);
    l0 += __shfl_xor_sync(0xffffffff, l0, 2);
    l1 += __shfl_xor_sync(0xffffffff, l1, 1);
    l1 += __shfl_xor_sync(0xffffffff, l1, 2);
    float inv0 = (lim0 > 0) ? 1.f / l0 : 0.f;
    float inv1 = (lim1 > 0) ? 1.f / l1 : 0.f;

    size_t base0 = ((size_t)(b * T_) + qg0) * D_ + h * DH_;
    size_t base1 = base0 + (size_t)8 * D_;
    #pragma unroll
    for (int j = 0; j < 8; j++) {
        int col = j * 8 + tig * 2;
        *(__half2*)(g_ctx16 + base0 + col) = __floats2half2_rn(oacc[j][0] * inv0, oacc[j][1] * inv0);
        *(__half2*)(g_ctx16 + base1 + col) = __floats2half2_rn(oacc[j][2] * inv1, oacc[j][3] * inv1);
    }
}

// ---------------------------------------------------------------------------
// Classifier v2 (out-proj fused away):
// logits = H@WcTop + ctx@Wfused + bc + (t>0 ? bo7 : 0)
// 8 warps/block, 4 rows per warp, grid 512.
// ---------------------------------------------------------------------------
__global__ __launch_bounds__(256) void classifier2(
    const float* __restrict__ H, const float* __restrict__ bc)
{
    __shared__ float sW[2 * C_ * D_];    // 43008 B
    const int tid = threadIdx.x;
    for (int i = tid; i < 2 * C_ * D_; i += 256) sW[i] = g_cls[i];
    __syncthreads();

    const int warp = tid >> 5, lane = tid & 31;
    const int row0 = blockIdx.x * 32 + warp * 4;

    float acc[4][C_] = {};

    // H part (fp32)
    #pragma unroll
    for (int i = 0; i < 6; i++) {
        int d0 = (i * 32 + lane) * 4;
        float4 hv[4];
        #pragma unroll
        for (int r = 0; r < 4; r++)
            hv[r] = *(const float4*)(H + (size_t)(row0 + r) * D_ + d0);
        #pragma unroll
        for (int c = 0; c < C_; c++) {
            float4 wv = *(const float4*)(sW + c * D_ + d0);
            #pragma unroll
            for (int r = 0; r < 4; r++)
                acc[r][c] += hv[r].x * wv.x + hv[r].y * wv.y + hv[r].z * wv.z + hv[r].w * wv.w;
        }
    }

    // ctx part (half)
    #pragma unroll
    for (int i = 0; i < 3; i++) {
        int d0 = (i * 32 + lane) * 8;
        float cv[4][8];
        #pragma unroll
        for (int r = 0; r < 4; r++) {
            uint4 u = *(const uint4*)(g_ctx16 + (size_t)(row0 + r) * D_ + d0);
            const __half2* hp = (const __half2*)&u;
            #pragma unroll
            for (int j = 0; j < 4; j++) {
                float2 f = __half22float2(hp[j]);
                cv[r][2 * j] = f.x; cv[r][2 * j + 1] = f.y;
            }
        }
        #pragma unroll
        for (int c = 0; c < C_; c++) {
            float4 w0 = *(const float4*)(sW + C_ * D_ + c * D_ + d0);
            float4 w1 = *(const float4*)(sW + C_ * D_ + c * D_ + d0 + 4);
            #pragma unroll
            for (int r = 0; r < 4; r++)
                acc[r][c] += cv[r][0] * w0.x + cv[r][1] * w0.y + cv[r][2] * w0.z + cv[r][3] * w0.w
                           + cv[r][4] * w1.x + cv[r][5] * w1.y + cv[r][6] * w1.z + cv[r][7] * w1.w;
        }
    }

    #pragma unroll
    for (int r = 0; r < 4; r++)
        #pragma unroll
        for (int c = 0; c < C_; c++) {
            float v = acc[r][c];
            v += __shfl_down_sync(0xffffffff, v, 16);
            v += __shfl_down_sync(0xffffffff, v, 8);
            v += __shfl_down_sync(0xffffffff, v, 4);
            v += __shfl_down_sync(0xffffffff, v, 2);
            v += __shfl_down_sync(0xffffffff, v, 1);
            acc[r][c] = v;
        }

    if (lane == 0) {
        #pragma unroll
        for (int r = 0; r < 4; r++) {
            int row = row0 + r;
            int t = row & (T_ - 1);
            #pragma unroll
            for (int c = 0; c < C_; c++) {
                float v = acc[r][c] + __ldg(bc + c);
                if (t > 0) v += g_bo7[c];
                g_all[(size_t)row * C_ + c] = v;
            }
        }
    }
}

// ---------------------------------------------------------------------------
__global__ void finalize_kernel(const int* __restrict__ nt, float* __restrict__ out,
                                int out_size)
{
    const int ALL = B_ * T_ * C_;
    const int FIN = B_ * C_;
    int i = blockIdx.x * blockDim.x + threadIdx.x;
    if (out_size >= ALL + FIN) {
        if (i < ALL) out[i] = g_all[i];
        if (i < FIN) {
            int b = i / C_, c = i - b * C_;
            int t = nt[b] - 1;
            out[ALL + i] = g_all[((size_t)(b * T_ + t)) * C_ + c];
        }
    } else if (out_size >= ALL) {
        if (i < ALL) out[i] = g_all[i];
    } else {
        if (i < FIN) {
            int b = i / C_, c = i - b * C_;
            int t = nt[b] - 1;
            out[i] = g_all[((size_t)(b * T_ + t)) * C_ + c];
        }
    }
}

// ---------------------------------------------------------------------------
extern "C" void kernel_launch(void* const* d_in, const int* in_sizes, int n_in,
                              void* d_out, int out_size)
{
    const float* H  = (const float*)d_in[0];
    const float* Wq = (const float*)d_in[1];
    const float* bq = (const float*)d_in[2];
    const float* Wk = (const float*)d_in[3];
    const float* bk = (const float*)d_in[4];
    const float* Wv = (const float*)d_in[5];
    const float* bv = (const float*)d_in[6];
    const float* Wo = (const float*)d_in[7];
    const float* bo = (const float*)d_in[8];
    const float* Wc = (const float*)d_in[9];
    const float* bc = (const float*)d_in[10];
    const int*   nt = (const int*)d_in[11];
    float* out = (float*)d_out;

    __half *ph16, *pq16, *pk16, *pv16, *pwt16;
    cudaGetSymbolAddress((void**)&ph16,   g_h16);
    cudaGetSymbolAddress((void**)&pq16,   g_q16);
    cudaGetSymbolAddress((void**)&pk16,   g_k16);
    cudaGetSymbolAddress((void**)&pv16,   g_v16);
    cudaGetSymbolAddress((void**)&pwt16,  g_wt16);

    const int M = B_ * T_;

    // 0) conversions + classifier-weight fusion prep
    const int n4 = M * D_ / 4;
    conv_f2h<<<(n4 + 255) / 256, 256>>>((const float4*)H, (__half2*)ph16, n4);
    transpose3<<<dim3(D_ / 32, D_ / 32, 3), dim3(32, 8)>>>(Wq, Wk, Wv);
    fuse_prep<<<8, 128>>>(Wo, Wc, bo);

    // 1) fused QKV -> half outputs
    dim3 qkv_grid(D_ / 128, M / 128, 3);
    f16_gemm_bias<<<qkv_grid, 256>>>(ph16, pwt16, bq, pq16, bk, pk16, bv, pv16);

    // 2) flash attention (tensor cores)
    attn_mma<<<dim3(NH_, B_, 4), 128>>>(nt);

    // 3) classifier (out-proj algebraically fused)
    classifier2<<<M / 32, 256>>>(H, bc);

    // 4) finalize
    const int ALL = B_ * T_ * C_;
    finalize_kernel<<<(ALL + 255) / 256, 256>>>(nt, out, out_size);
}

// round 15
// speedup vs baseline: 2.9970x; 1.0430x over previous
#include <cuda_runtime.h>
#include <cuda_fp16.h>
#include <cstdint>

#define B_ 64
#define T_ 256
#define D_ 768
#define NH_ 12
#define C_ 7
#define DH_ 64

// Scratch (device globals — no allocation allowed)
__device__ float  g_all[B_ * T_ * C_];
__device__ float  g_cls[2 * 7 * D_];       // [WcTopT (7x768)][WfusedT (7x768)]
__device__ float  g_bo7[8];
__device__ __half g_h16[B_ * T_ * D_];     // H in half
__device__ __half g_q16[B_ * T_ * D_];
__device__ __half g_k16[B_ * T_ * D_];
__device__ __half g_v16[B_ * T_ * D_];
__device__ __half g_ctx16[B_ * T_ * D_];   // attention output (half)
__device__ __half g_wt16[3 * D_ * D_];     // Wq^T,Wk^T,Wv^T (K-major, half)

// ---------------------------------------------------------------------------
__device__ __forceinline__ uint32_t smem_u32(const void* p) {
    uint32_t a;
    asm("{ .reg .u64 t; cvta.to.shared.u64 t, %1; cvt.u32.u64 %0, t; }" : "=r"(a) : "l"(p));
    return a;
}
__device__ __forceinline__ void cp_async16(uint32_t saddr, const void* src) {
    asm volatile("cp.async.cg.shared.global [%0], [%1], 16;" :: "r"(saddr), "l"(src) : "memory");
}
__device__ __forceinline__ void cp_commit() { asm volatile("cp.async.commit_group;" ::: "memory"); }
__device__ __forceinline__ void cp_wait0()  { asm volatile("cp.async.wait_group 0;" ::: "memory"); }
__device__ __forceinline__ void cp_wait2()  { asm volatile("cp.async.wait_group 2;" ::: "memory"); }

__device__ __forceinline__ void mma_f16(float c[4], const uint32_t a[4], const uint32_t b[2]) {
    asm volatile(
        "mma.sync.aligned.m16n8k16.row.col.f32.f16.f16.f32 "
        "{%0,%1,%2,%3},{%4,%5,%6,%7},{%8,%9},{%0,%1,%2,%3};"
        : "+f"(c[0]), "+f"(c[1]), "+f"(c[2]), "+f"(c[3])
        : "r"(a[0]), "r"(a[1]), "r"(a[2]), "r"(a[3]), "r"(b[0]), "r"(b[1]));
}
__device__ __forceinline__ void ldsm_x4(uint32_t& r0, uint32_t& r1, uint32_t& r2, uint32_t& r3,
                                        uint32_t addr) {
    asm volatile("ldmatrix.sync.aligned.m8n8.x4.shared.b16 {%0,%1,%2,%3}, [%4];"
                 : "=r"(r0), "=r"(r1), "=r"(r2), "=r"(r3) : "r"(addr));
}
__device__ __forceinline__ void ldsm_x4_t(uint32_t& r0, uint32_t& r1, uint32_t& r2, uint32_t& r3,
                                          uint32_t addr) {
    asm volatile("ldmatrix.sync.aligned.m8n8.x4.trans.shared.b16 {%0,%1,%2,%3}, [%4];"
                 : "=r"(r0), "=r"(r1), "=r"(r2), "=r"(r3) : "r"(addr));
}
__device__ __forceinline__ float ex2(float x) {
    float y; asm("ex2.approx.f32 %0, %1;" : "=f"(y) : "f"(x)); return y;
}
__device__ __forceinline__ uint32_t packh2(float lo, float hi) {
    uint32_t r;
    asm("cvt.rn.f16x2.f32 %0, %1, %2;" : "=r"(r) : "f"(hi), "f"(lo));
    return r;
}

// ---------------------------------------------------------------------------
// Conversions
// ---------------------------------------------------------------------------
__global__ void conv_f2h(const float4* __restrict__ src, __half2* __restrict__ dst, int n4)
{
    int i = blockIdx.x * blockDim.x + threadIdx.x;
    if (i < n4) {
        float4 v = src[i];
        dst[2 * i]     = __floats2half2_rn(v.x, v.y);
        dst[2 * i + 1] = __floats2half2_rn(v.z, v.w);
    }
}

// g_wt16[z][n][k] = (half) W_z[k][n]   (z = 0,1,2 -> Wq,Wk,Wv)
__global__ void transpose3(const float* __restrict__ Wq, const float* __restrict__ Wk,
                           const float* __restrict__ Wv)
{
    __shared__ float t[32][33];
    const float* src = (blockIdx.z == 0) ? Wq : (blockIdx.z == 1) ? Wk : Wv;
    __half* dst = g_wt16 + (size_t)blockIdx.z * D_ * D_;
    int x = blockIdx.x * 32 + threadIdx.x;
    int y = blockIdx.y * 32 + threadIdx.y;
    #pragma unroll
    for (int i = 0; i < 32; i += 8)
        t[threadIdx.y + i][threadIdx.x] = src[(size_t)(y + i) * D_ + x];
    __syncthreads();
    x = blockIdx.y * 32 + threadIdx.x;
    y = blockIdx.x * 32 + threadIdx.y;
    #pragma unroll
    for (int i = 0; i < 32; i += 8)
        dst[(size_t)(y + i) * D_ + x] = __float2half(t[threadIdx.x][threadIdx.y + i]);
}

// ---------------------------------------------------------------------------
// Prep: WcTopT[c][d] = Wc[d][c]; WfusedT[c][d] = sum_n Wo[d][n]*Wc[D+n][c];
//       bo7[c] = sum_n bo[n]*Wc[D+n][c]
// ---------------------------------------------------------------------------
__global__ void fuse_prep(const float* __restrict__ Wo, const float* __restrict__ Wc,
                          const float* __restrict__ bo)
{
    __shared__ float sWb[D_ * C_];
    const int tid = threadIdx.x;
    const int blk = blockIdx.x;
    if (blk < 6) {
        for (int i = tid; i < D_ * C_; i += 128) sWb[i] = Wc[D_ * C_ + i];
        __syncthreads();
        const int d = blk * 128 + tid;
        const float* wo = Wo + (size_t)d * D_;
        float acc[C_] = {};
        for (int n = 0; n < D_; n++) {
            float w = wo[n];
            #pragma unroll
            for (int c = 0; c < C_; c++) acc[c] = fmaf(w, sWb[n * C_ + c], acc[c]);
        }
        #pragma unroll
        for (int c = 0; c < C_; c++) g_cls[C_ * D_ + c * D_ + d] = acc[c];
    } else if (blk == 6) {
        for (int i = tid; i < D_ * C_; i += 128) {
            int c = i / D_, d = i - c * D_;
            g_cls[i] = Wc[d * C_ + c];
        }
    } else {
        if (tid < C_) {
            float a = 0.f;
            for (int n = 0; n < D_; n++) a = fmaf(bo[n], Wc[D_ * C_ + n * C_ + tid], a);
            g_bo7[tid] = a;
        }
    }
}

// ---------------------------------------------------------------------------
// FP16 tensor-core GEMM: Out[M,N] = A[M,K] @ WT[N,K]^T + bias[N] -> half out
// 4-stage cp.async pipeline (dynamic smem), one __syncthreads per K-iter.
// ---------------------------------------------------------------------------
#define HST 40
#define HSTAGE (128 * HST * 2 * 2)       // 20480 B per stage
#define NSTAGE 4
#define GEMM_SMEM (NSTAGE * HSTAGE)      // 81920 B
#define HBK 32
#define HKT (D_ / HBK)                   // 24

__global__ __launch_bounds__(256, 2) void f16_gemm_bias(
    const __half* __restrict__ A, const __half* __restrict__ WTbase,
    const float* __restrict__ b0, __half* __restrict__ O0,
    const float* __restrict__ b1, __half* __restrict__ O1,
    const float* __restrict__ b2, __half* __restrict__ O2)
{
    extern __shared__ __align__(16) char gsm[];
    const uint32_t sbase = smem_u32(gsm);

    const int tid = threadIdx.x;
    const int bx = blockIdx.x, by = blockIdx.y, bz = blockIdx.z;

    const __half* W    = WTbase + (size_t)bz * D_ * D_;
    const float*  bias = (bz == 0) ? b0 : (bz == 1) ? b1 : b2;
    __half*       Cout = (bz == 0) ? O0 : (bz == 1) ? O1 : O2;

    const int warp = tid >> 5;
    const int lane = tid & 31;
    const int gid = lane >> 2;
    const int tig = lane & 3;
    const int m0 = (warp & 3) * 32;
    const int n0 = (warp >> 2) * 64;

    const __half* Ag = A + (size_t)(by * 128) * D_;
    const __half* Wg = W + (size_t)(bx * 128) * D_;

    const int frow = tid >> 1;
    const int g0   = (tid & 1) * 2;

    const int a_r = ((lane >> 3) & 1) * 8 + (lane & 7);
    const int a_c = (lane >> 4) * 8;
    const int b_r = (lane >> 4) * 8 + (lane & 7);
    const int b_c = ((lane >> 3) & 1) * 8;
    const uint32_t aoff0 = ((m0 + a_r) * HST + a_c) * 2;
    const uint32_t boff0 = 128 * HST * 2 + ((n0 + b_r) * HST + b_c) * 2;

    float acc[2][8][4] = {};

    #define HFILL(buf, kt) do {                                                   \
        const uint32_t sa = sbase + (buf) * HSTAGE;                               \
        const uint32_t sb = sa + 128 * HST * 2;                                   \
        const int kb = (kt) * HBK;                                                \
        _Pragma("unroll")                                                         \
        for (int g = g0; g < g0 + 2; g++) {                                       \
            cp_async16(sa + frow * (HST * 2) + g * 16,                            \
                       Ag + (size_t)frow * D_ + kb + g * 8);                      \
            cp_async16(sb + frow * (HST * 2) + g * 16,                            \
                       Wg + (size_t)frow * D_ + kb + g * 8);                      \
        }                                                                         \
    } while (0)

    // prologue: stages 0..2 in flight (3 groups)
    HFILL(0, 0); cp_commit();
    HFILL(1, 1); cp_commit();
    HFILL(2, 2); cp_commit();

    for (int kt = 0; kt < HKT; kt++) {
        cp_wait2();          // group kt complete (<=2 pending)
        __syncthreads();     // stage kt visible to all; all warps left stage (kt-1)

        // fill stage (kt+3)&3 == (kt-1)&3 — safe: barrier above proves no readers
        if (kt + 3 < HKT) HFILL((kt + 3) & (NSTAGE - 1), kt + 3);
        cp_commit();         // always commit (empty groups keep wait accounting exact)

        const uint32_t stage = sbase + (kt & (NSTAGE - 1)) * HSTAGE;

        #pragma unroll
        for (int kk = 0; kk < HBK; kk += 16) {
            uint32_t a[2][4], b[8][2];
            ldsm_x4(a[0][0], a[0][1], a[0][2], a[0][3], stage + aoff0 + kk * 2);
            ldsm_x4(a[1][0], a[1][1], a[1][2], a[1][3], stage + aoff0 + 16 * HST * 2 + kk * 2);
            #pragma unroll
            for (int jp = 0; jp < 4; jp++)
                ldsm_x4(b[2 * jp][0], b[2 * jp][1], b[2 * jp + 1][0], b[2 * jp + 1][1],
                        stage + boff0 + jp * 16 * HST * 2 + kk * 2);
            #pragma unroll
            for (int mt = 0; mt < 2; mt++)
                #pragma unroll
                for (int nt = 0; nt < 8; nt++)
                    mma_f16(acc[mt][nt], a[mt], b[nt]);
        }
        // no trailing syncthreads: next iteration's barrier orders reuse
    }
    cp_wait0();

    #pragma unroll
    for (int mt = 0; mt < 2; mt++) {
        #pragma unroll
        for (int nt = 0; nt < 8; nt++) {
            int row = by * 128 + m0 + mt * 16 + gid;
            int col = bx * 128 + n0 + nt * 8 + tig * 2;
            float bx0 = bias[col], bx1 = bias[col + 1];
            *(__half2*)(Cout + (size_t)row * D_ + col) =
                __floats2half2_rn(acc[mt][nt][0] + bx0, acc[mt][nt][1] + bx1);
            *(__half2*)(Cout + (size_t)(row + 8) * D_ + col) =
                __floats2half2_rn(acc[mt][nt][2] + bx0, acc[mt][nt][3] + bx1);
        }
    }
}

// ---------------------------------------------------------------------------
// Flash attention (tensor cores, m16n8k16): block = 4 warps, 64-query tile.
// ---------------------------------------------------------------------------
__global__ __launch_bounds__(128) void attn_mma(const int* __restrict__ num_turns)
{
    const int h = blockIdx.x;
    const int b = blockIdx.y;
    const int qbase = blockIdx.z * 64;
    const int tid = threadIdx.x;
    const int w = tid >> 5;
    const int lane = tid & 31;
    const int gid = lane >> 2, tig = lane & 3;
    const int id = lane >> 3;

    __shared__ __half Qs[64][72];
    __shared__ __half Ks[64][72];
    __shared__ __half Vs[64][72];

    const int ntb = num_turns[b];
    int maxlim = qbase + 63; if (ntb < maxlim) maxlim = ntb;
    const int nchunks = (maxlim + 63) >> 6;

    {
        int row = tid >> 1, c0 = (tid & 1) * 32;
        const uint4* src = (const uint4*)(g_q16 + ((size_t)(b * T_) + qbase + row) * D_ + h * DH_ + c0);
        uint4* dst = (uint4*)&Qs[row][c0];
        #pragma unroll
        for (int i = 0; i < 4; i++) dst[i] = src[i];
    }
    __syncthreads();

    uint32_t aQ[4][4];
    #pragma unroll
    for (int ks = 0; ks < 4; ks++) {
        uint32_t addr = smem_u32(&Qs[w * 16 + (id & 1) * 8 + (lane & 7)][ks * 16 + (id >> 1) * 8]);
        ldsm_x4(aQ[ks][0], aQ[ks][1], aQ[ks][2], aQ[ks][3], addr);
    }

    const int qg0 = qbase + w * 16 + gid;
    const int lim0 = (qg0 < ntb) ? qg0 : ntb;
    const int lim1 = (qg0 + 8 < ntb) ? (qg0 + 8) : ntb;
    const float Cc = 0.18033688f;   // 0.125 * log2(e)

    float m0 = -1e30f, m1 = -1e30f, l0 = 0.f, l1 = 0.f;
    float oacc[8][4] = {};

    for (int ch = 0; ch < nchunks; ch++) {
        const int kbase = ch * 64;
        {
            int row = tid >> 1, c0 = (tid & 1) * 32;
            const uint4* ksrc = (const uint4*)(g_k16 + ((size_t)(b * T_) + kbase + row) * D_ + h * DH_ + c0);
            const uint4* vsrc = (const uint4*)(g_v16 + ((size_t)(b * T_) + kbase + row) * D_ + h * DH_ + c0);
            uint4* kd = (uint4*)&Ks[row][c0];
            uint4* vd = (uint4*)&Vs[row][c0];
            #pragma unroll
            for (int i = 0; i < 4; i++) { kd[i] = ksrc[i]; vd[i] = vsrc[i]; }
        }
        __syncthreads();

        float sacc[8][4] = {};
        #pragma unroll
        for (int ks = 0; ks < 4; ks++) {
            uint32_t bk[8][2];
            #pragma unroll
            for (int j = 0; j < 4; j++) {
                uint32_t addr = smem_u32(&Ks[j * 16 + (id >> 1) * 8 + (lane & 7)][ks * 16 + (id & 1) * 8]);
                ldsm_x4(bk[2 * j][0], bk[2 * j][1], bk[2 * j + 1][0], bk[2 * j + 1][1], addr);
            }
            #pragma unroll
            for (int j = 0; j < 8; j++)
                mma_f16(sacc[j], aQ[ks], bk[j]);
        }

        #pragma unroll
        for (int j = 0; j < 8; j++) {
            int c0 = kbase + j * 8 + tig * 2;
            if (c0     >= lim0) sacc[j][0] = -1e30f;
            if (c0 + 1 >= lim0) sacc[j][1] = -1e30f;
            if (c0     >= lim1) sacc[j][2] = -1e30f;
            if (c0 + 1 >= lim1) sacc[j][3] = -1e30f;
        }
        float mx0 = -1e30f, mx1 = -1e30f;
        #pragma unroll
        for (int j = 0; j < 8; j++) {
            mx0 = fmaxf(mx0, fmaxf(sacc[j][0], sacc[j][1]));
            mx1 = fmaxf(mx1, fmaxf(sacc[j][2], sacc[j][3]));
        }
        mx0 = fmaxf(mx0, __shfl_xor_sync(0xffffffff, mx0, 1));
        mx0 = fmaxf(mx0, __shfl_xor_sync(0xffffffff, mx0, 2));
        mx1 = fmaxf(mx1, __shfl_xor_sync(0xffffffff, mx1, 1));
        mx1 = fmaxf(mx1, __shfl_xor_sync(0xffffffff, mx1, 2));

        float mn0 = fmaxf(m0, mx0), mn1 = fmaxf(m1, mx1);
        float cr0 = ex2((m0 - mn0) * Cc), cr1 = ex2((m1 - mn1) * Cc);
        m0 = mn0; m1 = mn1;

        uint32_t pa[4][4];
        float rs0 = 0.f, rs1 = 0.f;
        #pragma unroll
        for (int j = 0; j < 8; j++) {
            float p0 = ex2((sacc[j][0] - m0) * Cc);
            float p1 = ex2((sacc[j][1] - m0) * Cc);
            float p2 = ex2((sacc[j][2] - m1) * Cc);
            float p3 = ex2((sacc[j][3] - m1) * Cc);
            rs0 += p0 + p1; rs1 += p2 + p3;
            uint32_t h01 = packh2(p0, p1), h23 = packh2(p2, p3);
            if ((j & 1) == 0) { pa[j >> 1][0] = h01; pa[j >> 1][1] = h23; }
            else              { pa[j >> 1][2] = h01; pa[j >> 1][3] = h23; }
        }
        l0 = l0 * cr0 + rs0;
        l1 = l1 * cr1 + rs1;
        #pragma unroll
        for (int j = 0; j < 8; j++) {
            oacc[j][0] *= cr0; oacc[j][1] *= cr0;
            oacc[j][2] *= cr1; oacc[j][3] *= cr1;
        }

        #pragma unroll
        for (int ks2 = 0; ks2 < 4; ks2++) {
            uint32_t bv[8][2];
            #pragma unroll
            for (int j = 0; j < 4; j++) {
                uint32_t addr = smem_u32(&Vs[ks2 * 16 + (id & 1) * 8 + (lane & 7)][j * 16 + (id >> 1) * 8]);
                ldsm_x4_t(bv[2 * j][0], bv[2 * j][1], bv[2 * j + 1][0], bv[2 * j + 1][1], addr);
            }
            #pragma unroll
            for (int j = 0; j < 8; j++)
                mma_f16(oacc[j], pa[ks2], bv[j]);
        }
        __syncthreads();
    }

    l0 += __shfl_xor_sync(0xffffffff, l0, 1);
    l0 += __shfl_xor_sync(0xffffffff, l0, 2);
    l1 += __shfl_xor_sync(0xffffffff, l1, 1);
    l1 += __shfl_xor_sync(0xffffffff, l1, 2);
    float inv0 = (lim0 > 0) ? 1.f / l0 : 0.f;
    float inv1 = (lim1 > 0) ? 1.f / l1 : 0.f;

    size_t base0 = ((size_t)(b * T_) + qg0) * D_ + h * DH_;
    size_t base1 = base0 + (size_t)8 * D_;
    #pragma unroll
    for (int j = 0; j < 8; j++) {
        int col = j * 8 + tig * 2;
        *(__half2*)(g_ctx16 + base0 + col) = __floats2half2_rn(oacc[j][0] * inv0, oacc[j][1] * inv0);
        *(__half2*)(g_ctx16 + base1 + col) = __floats2half2_rn(oacc[j][2] * inv1, oacc[j][3] * inv1);
    }
}

// ---------------------------------------------------------------------------
// Classifier v2: logits = H@WcTop + ctx@Wfused + bc + (t>0 ? bo7 : 0)
// ---------------------------------------------------------------------------
__global__ __launch_bounds__(256) void classifier2(
    const float* __restrict__ H, const float* __restrict__ bc)
{
    __shared__ float sW[2 * C_ * D_];
    const int tid = threadIdx.x;
    for (int i = tid; i < 2 * C_ * D_; i += 256) sW[i] = g_cls[i];
    __syncthreads();

    const int warp = tid >> 5, lane = tid & 31;
    const int row0 = blockIdx.x * 32 + warp * 4;

    float acc[4][C_] = {};

    #pragma unroll
    for (int i = 0; i < 6; i++) {
        int d0 = (i * 32 + lane) * 4;
        float4 hv[4];
        #pragma unroll
        for (int r = 0; r < 4; r++)
            hv[r] = *(const float4*)(H + (size_t)(row0 + r) * D_ + d0);
        #pragma unroll
        for (int c = 0; c < C_; c++) {
            float4 wv = *(const float4*)(sW + c * D_ + d0);
            #pragma unroll
            for (int r = 0; r < 4; r++)
                acc[r][c] += hv[r].x * wv.x + hv[r].y * wv.y + hv[r].z * wv.z + hv[r].w * wv.w;
        }
    }

    #pragma unroll
    for (int i = 0; i < 3; i++) {
        int d0 = (i * 32 + lane) * 8;
        float cv[4][8];
        #pragma unroll
        for (int r = 0; r < 4; r++) {
            uint4 u = *(const uint4*)(g_ctx16 + (size_t)(row0 + r) * D_ + d0);
            const __half2* hp = (const __half2*)&u;
            #pragma unroll
            for (int j = 0; j < 4; j++) {
                float2 f = __half22float2(hp[j]);
                cv[r][2 * j] = f.x; cv[r][2 * j + 1] = f.y;
            }
        }
        #pragma unroll
        for (int c = 0; c < C_; c++) {
            float4 w0 = *(const float4*)(sW + C_ * D_ + c * D_ + d0);
            float4 w1 = *(const float4*)(sW + C_ * D_ + c * D_ + d0 + 4);
            #pragma unroll
            for (int r = 0; r < 4; r++)
                acc[r][c] += cv[r][0] * w0.x + cv[r][1] * w0.y + cv[r][2] * w0.z + cv[r][3] * w0.w
                           + cv[r][4] * w1.x + cv[r][5] * w1.y + cv[r][6] * w1.z + cv[r][7] * w1.w;
        }
    }

    #pragma unroll
    for (int r = 0; r < 4; r++)
        #pragma unroll
        for (int c = 0; c < C_; c++) {
            float v = acc[r][c];
            v += __shfl_down_sync(0xffffffff, v, 16);
            v += __shfl_down_sync(0xffffffff, v, 8);
            v += __shfl_down_sync(0xffffffff, v, 4);
            v += __shfl_down_sync(0xffffffff, v, 2);
            v += __shfl_down_sync(0xffffffff, v, 1);
            acc[r][c] = v;
        }

    if (lane == 0) {
        #pragma unroll
        for (int r = 0; r < 4; r++) {
            int row = row0 + r;
            int t = row & (T_ - 1);
            #pragma unroll
            for (int c = 0; c < C_; c++) {
                float v = acc[r][c] + __ldg(bc + c);
                if (t > 0) v += g_bo7[c];
                g_all[(size_t)row * C_ + c] = v;
            }
        }
    }
}

// ---------------------------------------------------------------------------
__global__ void finalize_kernel(const int* __restrict__ nt, float* __restrict__ out,
                                int out_size)
{
    const int ALL = B_ * T_ * C_;
    const int FIN = B_ * C_;
    int i = blockIdx.x * blockDim.x + threadIdx.x;
    if (out_size >= ALL + FIN) {
        if (i < ALL) out[i] = g_all[i];
        if (i < FIN) {
            int b = i / C_, c = i - b * C_;
            int t = nt[b] - 1;
            out[ALL + i] = g_all[((size_t)(b * T_ + t)) * C_ + c];
        }
    } else if (out_size >= ALL) {
        if (i < ALL) out[i] = g_all[i];
    } else {
        if (i < FIN) {
            int b = i / C_, c = i - b * C_;
            int t = nt[b] - 1;
            out[i] = g_all[((size_t)(b * T_ + t)) * C_ + c];
        }
    }
}

// ---------------------------------------------------------------------------
extern "C" void kernel_launch(void* const* d_in, const int* in_sizes, int n_in,
                              void* d_out, int out_size)
{
    const float* H  = (const float*)d_in[0];
    const float* Wq = (const float*)d_in[1];
    const float* bq = (const float*)d_in[2];
    const float* Wk = (const float*)d_in[3];
    const float* bk = (const float*)d_in[4];
    const float* Wv = (const float*)d_in[5];
    const float* bv = (const float*)d_in[6];
    const float* Wo = (const float*)d_in[7];
    const float* bo = (const float*)d_in[8];
    const float* Wc = (const float*)d_in[9];
    const float* bc = (const float*)d_in[10];
    const int*   nt = (const int*)d_in[11];
    float* out = (float*)d_out;

    __half *ph16, *pq16, *pk16, *pv16, *pwt16;
    cudaGetSymbolAddress((void**)&ph16,   g_h16);
    cudaGetSymbolAddress((void**)&pq16,   g_q16);
    cudaGetSymbolAddress((void**)&pk16,   g_k16);
    cudaGetSymbolAddress((void**)&pv16,   g_v16);
    cudaGetSymbolAddress((void**)&pwt16,  g_wt16);

    cudaFuncSetAttribute(f16_gemm_bias,
                         cudaFuncAttributeMaxDynamicSharedMemorySize, GEMM_SMEM);

    const int M = B_ * T_;

    // 0) conversions + classifier-weight fusion prep
    const int n4 = M * D_ / 4;
    conv_f2h<<<(n4 + 255) / 256, 256>>>((const float4*)H, (__half2*)ph16, n4);
    transpose3<<<dim3(D_ / 32, D_ / 32, 3), dim3(32, 8)>>>(Wq, Wk, Wv);
    fuse_prep<<<8, 128>>>(Wo, Wc, bo);

    // 1) fused QKV -> half outputs (4-stage pipeline, dynamic smem)
    dim3 qkv_grid(D_ / 128, M / 128, 3);
    f16_gemm_bias<<<qkv_grid, 256, GEMM_SMEM>>>(ph16, pwt16, bq, pq16, bk, pk16, bv, pv16);

    // 2) flash attention (tensor cores)
    attn_mma<<<dim3(NH_, B_, 4), 128>>>(nt);

    // 3) classifier (out-proj algebraically fused)
    classifier2<<<M / 32, 256>>>(H, bc);

    // 4) finalize
    const int ALL = B_ * T_ * C_;
    finalize_kernel<<<(ALL + 255) / 256, 256>>>(nt, out, out_size);
}

// round 16
// speedup vs baseline: 3.0048x; 1.0026x over previous
#include <cuda_runtime.h>
#include <cuda_fp16.h>
#include <cstdint>

#define B_ 64
#define T_ 256
#define D_ 768
#define NH_ 12
#define C_ 7
#define DH_ 64

// Scratch (device globals — no allocation allowed)
__device__ float  g_all[B_ * T_ * C_];
__device__ float  g_cls[2 * 7 * D_];       // [WcTopT (7x768)][WfusedT (7x768)]
__device__ float  g_bo7[8];
__device__ __half g_h16[B_ * T_ * D_];     // H in half
__device__ __half g_q16[B_ * T_ * D_];
__device__ __half g_k16[B_ * T_ * D_];
__device__ __half g_v16[B_ * T_ * D_];
__device__ __half g_ctx16[B_ * T_ * D_];   // attention output (half)
__device__ __half g_wt16[3 * D_ * D_];     // Wq^T,Wk^T,Wv^T (K-major, half)

// ---------------------------------------------------------------------------
__device__ __forceinline__ uint32_t smem_u32(const void* p) {
    uint32_t a;
    asm("{ .reg .u64 t; cvta.to.shared.u64 t, %1; cvt.u32.u64 %0, t; }" : "=r"(a) : "l"(p));
    return a;
}
__device__ __forceinline__ void cp_async16(uint32_t saddr, const void* src) {
    asm volatile("cp.async.cg.shared.global [%0], [%1], 16;" :: "r"(saddr), "l"(src) : "memory");
}
__device__ __forceinline__ void cp_commit() { asm volatile("cp.async.commit_group;" ::: "memory"); }
__device__ __forceinline__ void cp_wait0()  { asm volatile("cp.async.wait_group 0;" ::: "memory"); }
__device__ __forceinline__ void cp_wait2()  { asm volatile("cp.async.wait_group 2;" ::: "memory"); }

__device__ __forceinline__ void mma_f16(float c[4], const uint32_t a[4], const uint32_t b[2]) {
    asm volatile(
        "mma.sync.aligned.m16n8k16.row.col.f32.f16.f16.f32 "
        "{%0,%1,%2,%3},{%4,%5,%6,%7},{%8,%9},{%0,%1,%2,%3};"
        : "+f"(c[0]), "+f"(c[1]), "+f"(c[2]), "+f"(c[3])
        : "r"(a[0]), "r"(a[1]), "r"(a[2]), "r"(a[3]), "r"(b[0]), "r"(b[1]));
}
__device__ __forceinline__ void ldsm_x4(uint32_t& r0, uint32_t& r1, uint32_t& r2, uint32_t& r3,
                                        uint32_t addr) {
    asm volatile("ldmatrix.sync.aligned.m8n8.x4.shared.b16 {%0,%1,%2,%3}, [%4];"
                 : "=r"(r0), "=r"(r1), "=r"(r2), "=r"(r3) : "r"(addr));
}
__device__ __forceinline__ void ldsm_x4_t(uint32_t& r0, uint32_t& r1, uint32_t& r2, uint32_t& r3,
                                          uint32_t addr) {
    asm volatile("ldmatrix.sync.aligned.m8n8.x4.trans.shared.b16 {%0,%1,%2,%3}, [%4];"
                 : "=r"(r0), "=r"(r1), "=r"(r2), "=r"(r3) : "r"(addr));
}
__device__ __forceinline__ float ex2(float x) {
    float y; asm("ex2.approx.f32 %0, %1;" : "=f"(y) : "f"(x)); return y;
}
__device__ __forceinline__ uint32_t packh2(float lo, float hi) {
    uint32_t r;
    asm("cvt.rn.f16x2.f32 %0, %1, %2;" : "=r"(r) : "f"(hi), "f"(lo));
    return r;
}

// ---------------------------------------------------------------------------
// Conversions
// ---------------------------------------------------------------------------
__global__ void conv_f2h(const float4* __restrict__ src, __half2* __restrict__ dst, int n4)
{
    int i = blockIdx.x * blockDim.x + threadIdx.x;
    if (i < n4) {
        float4 v = src[i];
        dst[2 * i]     = __floats2half2_rn(v.x, v.y);
        dst[2 * i + 1] = __floats2half2_rn(v.z, v.w);
    }
}

// g_wt16[z][n][k] = (half) W_z[k][n]   (z = 0,1,2 -> Wq,Wk,Wv)
__global__ void transpose3(const float* __restrict__ Wq, const float* __restrict__ Wk,
                           const float* __restrict__ Wv)
{
    __shared__ float t[32][33];
    const float* src = (blockIdx.z == 0) ? Wq : (blockIdx.z == 1) ? Wk : Wv;
    __half* dst = g_wt16 + (size_t)blockIdx.z * D_ * D_;
    int x = blockIdx.x * 32 + threadIdx.x;
    int y = blockIdx.y * 32 + threadIdx.y;
    #pragma unroll
    for (int i = 0; i < 32; i += 8)
        t[threadIdx.y + i][threadIdx.x] = src[(size_t)(y + i) * D_ + x];
    __syncthreads();
    x = blockIdx.y * 32 + threadIdx.x;
    y = blockIdx.x * 32 + threadIdx.y;
    #pragma unroll
    for (int i = 0; i < 32; i += 8)
        dst[(size_t)(y + i) * D_ + x] = __float2half(t[threadIdx.x][threadIdx.y + i]);
}

// ---------------------------------------------------------------------------
// Prep: WcTopT[c][d] = Wc[d][c]; WfusedT[c][d] = sum_n Wo[d][n]*Wc[D+n][c];
//       bo7[c] = sum_n bo[n]*Wc[D+n][c]
// ---------------------------------------------------------------------------
__global__ void fuse_prep(const float* __restrict__ Wo, const float* __restrict__ Wc,
                          const float* __restrict__ bo)
{
    __shared__ float sWb[D_ * C_];
    const int tid = threadIdx.x;
    const int blk = blockIdx.x;
    if (blk < 6) {
        for (int i = tid; i < D_ * C_; i += 128) sWb[i] = Wc[D_ * C_ + i];
        __syncthreads();
        const int d = blk * 128 + tid;
        const float* wo = Wo + (size_t)d * D_;
        float acc[C_] = {};
        for (int n = 0; n < D_; n++) {
            float w = wo[n];
            #pragma unroll
            for (int c = 0; c < C_; c++) acc[c] = fmaf(w, sWb[n * C_ + c], acc[c]);
        }
        #pragma unroll
        for (int c = 0; c < C_; c++) g_cls[C_ * D_ + c * D_ + d] = acc[c];
    } else if (blk == 6) {
        for (int i = tid; i < D_ * C_; i += 128) {
            int c = i / D_, d = i - c * D_;
            g_cls[i] = Wc[d * C_ + c];
        }
    } else {
        if (tid < C_) {
            float a = 0.f;
            for (int n = 0; n < D_; n++) a = fmaf(bo[n], Wc[D_ * C_ + n * C_ + tid], a);
            g_bo7[tid] = a;
        }
    }
}

// ---------------------------------------------------------------------------
// FP16 tensor-core GEMM: Out[M,N] = A[M,K] @ WT[N,K]^T + bias[N] -> half out
// Block tile 256(M) x 128(N), 8 warps of 64x64. 4-stage cp.async pipeline.
// ---------------------------------------------------------------------------
#define HST 40
#define AROWS 256
#define BROWS 128
#define STAGEB ((AROWS + BROWS) * HST * 2)   // 30720 B per stage
#define NSTAGE 4
#define GEMM_SMEM (NSTAGE * STAGEB)          // 122880 B
#define HBK 32
#define HKT (D_ / HBK)                       // 24

__global__ __launch_bounds__(256, 1) void f16_gemm_bias(
    const __half* __restrict__ A, const __half* __restrict__ WTbase,
    const float* __restrict__ b0, __half* __restrict__ O0,
    const float* __restrict__ b1, __half* __restrict__ O1,
    const float* __restrict__ b2, __half* __restrict__ O2)
{
    extern __shared__ __align__(16) char gsm[];
    const uint32_t sbase = smem_u32(gsm);

    const int tid = threadIdx.x;
    const int bx = blockIdx.x, by = blockIdx.y, bz = blockIdx.z;

    const __half* W    = WTbase + (size_t)bz * D_ * D_;
    const float*  bias = (bz == 0) ? b0 : (bz == 1) ? b1 : b2;
    __half*       Cout = (bz == 0) ? O0 : (bz == 1) ? O1 : O2;

    const int warp = tid >> 5;
    const int lane = tid & 31;
    const int gid = lane >> 2;
    const int tig = lane & 3;
    const int m0 = (warp & 3) * 64;       // warp m offset in 256
    const int n0 = (warp >> 2) * 64;      // warp n offset in 128

    const __half* Ag = A + (size_t)(by * AROWS) * D_;
    const __half* Wg = W + (size_t)(bx * BROWS) * D_;

    const int frow = tid >> 1;            // 0..127
    const int g0   = (tid & 1) * 2;       // 16B-seg base within 64B row-chunk

    // ldmatrix lane maps
    const int a_r = ((lane >> 3) & 1) * 8 + (lane & 7);
    const int a_c = (lane >> 4) * 8;
    const int b_r = (lane >> 4) * 8 + (lane & 7);
    const int b_c = ((lane >> 3) & 1) * 8;
    const uint32_t aoff0 = ((m0 + a_r) * HST + a_c) * 2;
    const uint32_t boff0 = AROWS * HST * 2 + ((n0 + b_r) * HST + b_c) * 2;

    float acc[4][8][4] = {};   // 128 regs

    #define HFILL(buf, kt) do {                                                   \
        const uint32_t sa = sbase + (buf) * STAGEB;                               \
        const uint32_t sb = sa + AROWS * HST * 2;                                 \
        const int kb = (kt) * HBK;                                                \
        _Pragma("unroll")                                                         \
        for (int g = g0; g < g0 + 2; g++) {                                       \
            cp_async16(sa + frow * (HST * 2) + g * 16,                            \
                       Ag + (size_t)frow * D_ + kb + g * 8);                      \
            cp_async16(sa + (frow + 128) * (HST * 2) + g * 16,                    \
                       Ag + (size_t)(frow + 128) * D_ + kb + g * 8);              \
            cp_async16(sb + frow * (HST * 2) + g * 16,                            \
                       Wg + (size_t)frow * D_ + kb + g * 8);                      \
        }                                                                         \
    } while (0)

    HFILL(0, 0); cp_commit();
    HFILL(1, 1); cp_commit();
    HFILL(2, 2); cp_commit();

    for (int kt = 0; kt < HKT; kt++) {
        cp_wait2();          // group kt complete
        __syncthreads();     // stage kt visible; all warps left stage (kt-1)

        if (kt + 3 < HKT) HFILL((kt + 3) & (NSTAGE - 1), kt + 3);
        cp_commit();         // empty groups keep accounting exact

        const uint32_t stage = sbase + (kt & (NSTAGE - 1)) * STAGEB;

        #pragma unroll
        for (int kk = 0; kk < HBK; kk += 16) {
            uint32_t a[4][4], b[8][2];
            #pragma unroll
            for (int mt = 0; mt < 4; mt++)
                ldsm_x4(a[mt][0], a[mt][1], a[mt][2], a[mt][3],
                        stage + aoff0 + mt * 16 * HST * 2 + kk * 2);
            #pragma unroll
            for (int jp = 0; jp < 4; jp++)
                ldsm_x4(b[2 * jp][0], b[2 * jp][1], b[2 * jp + 1][0], b[2 * jp + 1][1],
                        stage + boff0 + jp * 16 * HST * 2 + kk * 2);
            #pragma unroll
            for (int mt = 0; mt < 4; mt++)
                #pragma unroll
                for (int nt = 0; nt < 8; nt++)
                    mma_f16(acc[mt][nt], a[mt], b[nt]);
        }
    }
    cp_wait0();

    #pragma unroll
    for (int mt = 0; mt < 4; mt++) {
        #pragma unroll
        for (int nt = 0; nt < 8; nt++) {
            int row = by * AROWS + m0 + mt * 16 + gid;
            int col = bx * BROWS + n0 + nt * 8 + tig * 2;
            float bx0 = bias[col], bx1 = bias[col + 1];
            *(__half2*)(Cout + (size_t)row * D_ + col) =
                __floats2half2_rn(acc[mt][nt][0] + bx0, acc[mt][nt][1] + bx1);
            *(__half2*)(Cout + (size_t)(row + 8) * D_ + col) =
                __floats2half2_rn(acc[mt][nt][2] + bx0, acc[mt][nt][3] + bx1);
        }
    }
}

// ---------------------------------------------------------------------------
// Flash attention (tensor cores, m16n8k16): block = 4 warps, 64-query tile.
// ---------------------------------------------------------------------------
__global__ __launch_bounds__(128) void attn_mma(const int* __restrict__ num_turns)
{
    const int h = blockIdx.x;
    const int b = blockIdx.y;
    const int qbase = blockIdx.z * 64;
    const int tid = threadIdx.x;
    const int w = tid >> 5;
    const int lane = tid & 31;
    const int gid = lane >> 2, tig = lane & 3;
    const int id = lane >> 3;

    __shared__ __half Qs[64][72];
    __shared__ __half Ks[64][72];
    __shared__ __half Vs[64][72];

    const int ntb = num_turns[b];
    int maxlim = qbase + 63; if (ntb < maxlim) maxlim = ntb;
    const int nchunks = (maxlim + 63) >> 6;

    {
        int row = tid >> 1, c0 = (tid & 1) * 32;
        const uint4* src = (const uint4*)(g_q16 + ((size_t)(b * T_) + qbase + row) * D_ + h * DH_ + c0);
        uint4* dst = (uint4*)&Qs[row][c0];
        #pragma unroll
        for (int i = 0; i < 4; i++) dst[i] = src[i];
    }
    __syncthreads();

    uint32_t aQ[4][4];
    #pragma unroll
    for (int ks = 0; ks < 4; ks++) {
        uint32_t addr = smem_u32(&Qs[w * 16 + (id & 1) * 8 + (lane & 7)][ks * 16 + (id >> 1) * 8]);
        ldsm_x4(aQ[ks][0], aQ[ks][1], aQ[ks][2], aQ[ks][3], addr);
    }

    const int qg0 = qbase + w * 16 + gid;
    const int lim0 = (qg0 < ntb) ? qg0 : ntb;
    const int lim1 = (qg0 + 8 < ntb) ? (qg0 + 8) : ntb;
    const float Cc = 0.18033688f;   // 0.125 * log2(e)

    float m0 = -1e30f, m1 = -1e30f, l0 = 0.f, l1 = 0.f;
    float oacc[8][4] = {};

    for (int ch = 0; ch < nchunks; ch++) {
        const int kbase = ch * 64;
        {
            int row = tid >> 1, c0 = (tid & 1) * 32;
            const uint4* ksrc = (const uint4*)(g_k16 + ((size_t)(b * T_) + kbase + row) * D_ + h * DH_ + c0);
            const uint4* vsrc = (const uint4*)(g_v16 + ((size_t)(b * T_) + kbase + row) * D_ + h * DH_ + c0);
            uint4* kd = (uint4*)&Ks[row][c0];
            uint4* vd = (uint4*)&Vs[row][c0];
            #pragma unroll
            for (int i = 0; i < 4; i++) { kd[i] = ksrc[i]; vd[i] = vsrc[i]; }
        }
        __syncthreads();

        float sacc[8][4] = {};
        #pragma unroll
        for (int ks = 0; ks < 4; ks++) {
            uint32_t bk[8][2];
            #pragma unroll
            for (int j = 0; j < 4; j++) {
                uint32_t addr = smem_u32(&Ks[j * 16 + (id >> 1) * 8 + (lane & 7)][ks * 16 + (id & 1) * 8]);
                ldsm_x4(bk[2 * j][0], bk[2 * j][1], bk[2 * j + 1][0], bk[2 * j + 1][1], addr);
            }
            #pragma unroll
            for (int j = 0; j < 8; j++)
                mma_f16(sacc[j], aQ[ks], bk[j]);
        }

        #pragma unroll
        for (int j = 0; j < 8; j++) {
            int c0 = kbase + j * 8 + tig * 2;
            if (c0     >= lim0) sacc[j][0] = -1e30f;
            if (c0 + 1 >= lim0) sacc[j][1] = -1e30f;
            if (c0     >= lim1) sacc[j][2] = -1e30f;
            if (c0 + 1 >= lim1) sacc[j][3] = -1e30f;
        }
        float mx0 = -1e30f, mx1 = -1e30f;
        #pragma unroll
        for (int j = 0; j < 8; j++) {
            mx0 = fmaxf(mx0, fmaxf(sacc[j][0], sacc[j][1]));
            mx1 = fmaxf(mx1, fmaxf(sacc[j][2], sacc[j][3]));
        }
        mx0 = fmaxf(mx0, __shfl_xor_sync(0xffffffff, mx0, 1));
        mx0 = fmaxf(mx0, __shfl_xor_sync(0xffffffff, mx0, 2));
        mx1 = fmaxf(mx1, __shfl_xor_sync(0xffffffff, mx1, 1));
        mx1 = fmaxf(mx1, __shfl_xor_sync(0xffffffff, mx1, 2));

        float mn0 = fmaxf(m0, mx0), mn1 = fmaxf(m1, mx1);
        float cr0 = ex2((m0 - mn0) * Cc), cr1 = ex2((m1 - mn1) * Cc);
        m0 = mn0; m1 = mn1;

        uint32_t pa[4][4];
        float rs0 = 0.f, rs1 = 0.f;
        #pragma unroll
        for (int j = 0; j < 8; j++) {
            float p0 = ex2((sacc[j][0] - m0) * Cc);
            float p1 = ex2((sacc[j][1] - m0) * Cc);
            float p2 = ex2((sacc[j][2] - m1) * Cc);
            float p3 = ex2((sacc[j][3] - m1) * Cc);
            rs0 += p0 + p1; rs1 += p2 + p3;
            uint32_t h01 = packh2(p0, p1), h23 = packh2(p2, p3);
            if ((j & 1) == 0) { pa[j >> 1][0] = h01; pa[j >> 1][1] = h23; }
            else              { pa[j >> 1][2] = h01; pa[j >> 1][3] = h23; }
        }
        l0 = l0 * cr0 + rs0;
        l1 = l1 * cr1 + rs1;
        #pragma unroll
        for (int j = 0; j < 8; j++) {
            oacc[j][0] *= cr0; oacc[j][1] *= cr0;
            oacc[j][2] *= cr1; oacc[j][3] *= cr1;
        }

        #pragma unroll
        for (int ks2 = 0; ks2 < 4; ks2++) {
            uint32_t bv[8][2];
            #pragma unroll
            for (int j = 0; j < 4; j++) {
                uint32_t addr = smem_u32(&Vs[ks2 * 16 + (id & 1) * 8 + (lane & 7)][j * 16 + (id >> 1) * 8]);
                ldsm_x4_t(bv[2 * j][0], bv[2 * j][1], bv[2 * j + 1][0], bv[2 * j + 1][1], addr);
            }
            #pragma unroll
            for (int j = 0; j < 8; j++)
                mma_f16(oacc[j], pa[ks2], bv[j]);
        }
        __syncthreads();
    }

    l0 += __shfl_xor_sync(0xffffffff, l0, 1);
    l0 += __shfl_xor_sync(0xffffffff, l0, 2);
    l1 += __shfl_xor_sync(0xffffffff, l1, 1);
    l1 += __shfl_xor_sync(0xffffffff, l1, 2);
    float inv0 = (lim0 > 0) ? 1.f / l0 : 0.f;
    float inv1 = (lim1 > 0) ? 1.f / l1 : 0.f;

    size_t base0 = ((size_t)(b * T_) + qg0) * D_ + h * DH_;
    size_t base1 = base0 + (size_t)8 * D_;
    #pragma unroll
    for (int j = 0; j < 8; j++) {
        int col = j * 8 + tig * 2;
        *(__half2*)(g_ctx16 + base0 + col) = __floats2half2_rn(oacc[j][0] * inv0, oacc[j][1] * inv0);
        *(__half2*)(g_ctx16 + base1 + col) = __floats2half2_rn(oacc[j][2] * inv1, oacc[j][3] * inv1);
    }
}

// ---------------------------------------------------------------------------
// Classifier v2: logits = H@WcTop + ctx@Wfused + bc + (t>0 ? bo7 : 0)
// ---------------------------------------------------------------------------
__global__ __launch_bounds__(256) void classifier2(
    const float* __restrict__ H, const float* __restrict__ bc)
{
    __shared__ float sW[2 * C_ * D_];
    const int tid = threadIdx.x;
    for (int i = tid; i < 2 * C_ * D_; i += 256) sW[i] = g_cls[i];
    __syncthreads();

    const int warp = tid >> 5, lane = tid & 31;
    const int row0 = blockIdx.x * 32 + warp * 4;

    float acc[4][C_] = {};

    #pragma unroll
    for (int i = 0; i < 6; i++) {
        int d0 = (i * 32 + lane) * 4;
        float4 hv[4];
        #pragma unroll
        for (int r = 0; r < 4; r++)
            hv[r] = *(const float4*)(H + (size_t)(row0 + r) * D_ + d0);
        #pragma unroll
        for (int c = 0; c < C_; c++) {
            float4 wv = *(const float4*)(sW + c * D_ + d0);
            #pragma unroll
            for (int r = 0; r < 4; r++)
                acc[r][c] += hv[r].x * wv.x + hv[r].y * wv.y + hv[r].z * wv.z + hv[r].w * wv.w;
        }
    }

    #pragma unroll
    for (int i = 0; i < 3; i++) {
        int d0 = (i * 32 + lane) * 8;
        float cv[4][8];
        #pragma unroll
        for (int r = 0; r < 4; r++) {
            uint4 u = *(const uint4*)(g_ctx16 + (size_t)(row0 + r) * D_ + d0);
            const __half2* hp = (const __half2*)&u;
            #pragma unroll
            for (int j = 0; j < 4; j++) {
                float2 f = __half22float2(hp[j]);
                cv[r][2 * j] = f.x; cv[r][2 * j + 1] = f.y;
            }
        }
        #pragma unroll
        for (int c = 0; c < C_; c++) {
            float4 w0 = *(const float4*)(sW + C_ * D_ + c * D_ + d0);
            float4 w1 = *(const float4*)(sW + C_ * D_ + c * D_ + d0 + 4);
            #pragma unroll
            for (int r = 0; r < 4; r++)
                acc[r][c] += cv[r][0] * w0.x + cv[r][1] * w0.y + cv[r][2] * w0.z + cv[r][3] * w0.w
                           + cv[r][4] * w1.x + cv[r][5] * w1.y + cv[r][6] * w1.z + cv[r][7] * w1.w;
        }
    }

    #pragma unroll
    for (int r = 0; r < 4; r++)
        #pragma unroll
        for (int c = 0; c < C_; c++) {
            float v = acc[r][c];
            v += __shfl_down_sync(0xffffffff, v, 16);
            v += __shfl_down_sync(0xffffffff, v, 8);
            v += __shfl_down_sync(0xffffffff, v, 4);
            v += __shfl_down_sync(0xffffffff, v, 2);
            v += __shfl_down_sync(0xffffffff, v, 1);
            acc[r][c] = v;
        }

    if (lane == 0) {
        #pragma unroll
        for (int r = 0; r < 4; r++) {
            int row = row0 + r;
            int t = row & (T_ - 1);
            #pragma unroll
            for (int c = 0; c < C_; c++) {
                float v = acc[r][c] + __ldg(bc + c);
                if (t > 0) v += g_bo7[c];
                g_all[(size_t)row * C_ + c] = v;
            }
        }
    }
}

// ---------------------------------------------------------------------------
__global__ void finalize_kernel(const int* __restrict__ nt, float* __restrict__ out,
                                int out_size)
{
    const int ALL = B_ * T_ * C_;
    const int FIN = B_ * C_;
    int i = blockIdx.x * blockDim.x + threadIdx.x;
    if (out_size >= ALL + FIN) {
        if (i < ALL) out[i] = g_all[i];
        if (i < FIN) {
            int b = i / C_, c = i - b * C_;
            int t = nt[b] - 1;
            out[ALL + i] = g_all[((size_t)(b * T_ + t)) * C_ + c];
        }
    } else if (out_size >= ALL) {
        if (i < ALL) out[i] = g_all[i];
    } else {
        if (i < FIN) {
            int b = i / C_, c = i - b * C_;
            int t = nt[b] - 1;
            out[i] = g_all[((size_t)(b * T_ + t)) * C_ + c];
        }
    }
}

// ---------------------------------------------------------------------------
extern "C" void kernel_launch(void* const* d_in, const int* in_sizes, int n_in,
                              void* d_out, int out_size)
{
    const float* H  = (const float*)d_in[0];
    const float* Wq = (const float*)d_in[1];
    const float* bq = (const float*)d_in[2];
    const float* Wk = (const float*)d_in[3];
    const float* bk = (const float*)d_in[4];
    const float* Wv = (const float*)d_in[5];
    const float* bv = (const float*)d_in[6];
    const float* Wo = (const float*)d_in[7];
    const float* bo = (const float*)d_in[8];
    const float* Wc = (const float*)d_in[9];
    const float* bc = (const float*)d_in[10];
    const int*   nt = (const int*)d_in[11];
    float* out = (float*)d_out;

    __half *ph16, *pq16, *pk16, *pv16, *pwt16;
    cudaGetSymbolAddress((void**)&ph16,   g_h16);
    cudaGetSymbolAddress((void**)&pq16,   g_q16);
    cudaGetSymbolAddress((void**)&pk16,   g_k16);
    cudaGetSymbolAddress((void**)&pv16,   g_v16);
    cudaGetSymbolAddress((void**)&pwt16,  g_wt16);

    cudaFuncSetAttribute(f16_gemm_bias,
                         cudaFuncAttributeMaxDynamicSharedMemorySize, GEMM_SMEM);

    const int M = B_ * T_;

    // 0) conversions + classifier-weight fusion prep
    const int n4 = M * D_ / 4;
    conv_f2h<<<(n4 + 255) / 256, 256>>>((const float4*)H, (__half2*)ph16, n4);
    transpose3<<<dim3(D_ / 32, D_ / 32, 3), dim3(32, 8)>>>(Wq, Wk, Wv);
    fuse_prep<<<8, 128>>>(Wo, Wc, bo);

    // 1) fused QKV -> half outputs (256x128 block tile, 64x64 warp tiles)
    dim3 qkv_grid(D_ / BROWS, M / AROWS, 3);   // (6, 64, 3)
    f16_gemm_bias<<<qkv_grid, 256, GEMM_SMEM>>>(ph16, pwt16, bq, pq16, bk, pk16, bv, pv16);

    // 2) flash attention (tensor cores)
    attn_mma<<<dim3(NH_, B_, 4), 128>>>(nt);

    // 3) classifier (out-proj algebraically fused)
    classifier2<<<M / 32, 256>>>(H, bc);

    // 4) finalize
    const int ALL = B_ * T_ * C_;
    finalize_kernel<<<(ALL + 255) / 256, 256>>>(nt, out, out_size);
}